// round 5
// baseline (speedup 1.0000x reference)
#include <cuda_runtime.h>
#include <cstdint>
#include <math.h>

// Problem constants
#define NB 16
#define NQ 1024
#define NKK 1024
#define DM 512
#define NH 8
#define DKH 64
#define NM 40
#define NKP 1088          // padded key length: 17 * 64
#define ROWS (NB*NQ)      // 16384

// -------- scratch (static device memory: allowed) --------
__device__ float g_Q[(size_t)NB*NH*NQ*DKH];     // [bh][1024][64] fp32
__device__ float g_K[(size_t)NB*NH*NKP*DKH];    // [bh][1088][64] tf32 bits
__device__ float g_V[(size_t)NB*NH*NKP*DKH];    // [bh][1088][64] tf32 bits
__device__ float g_O[(size_t)ROWS*DM];          // attention out
__device__ float g_X[(size_t)ROWS*DM];          // proj + residual
__device__ float g_Wt[4][(size_t)DM*DM];        // transposed weights [n][k]

// ============================================================
// helpers (base-ISA only: mma.sync)
// ============================================================
__device__ __forceinline__ uint32_t f2tf32(float f) {
    uint32_t r;
    asm("cvt.rna.tf32.f32 %0, %1;" : "=r"(r) : "f"(f));
    return r;
}
__device__ __forceinline__ float ex2f(float x) {
    float y;
    asm("ex2.approx.f32 %0, %1;" : "=f"(y) : "f"(x));
    return y;
}
__device__ __forceinline__ void mma_tf32(float* c, const uint32_t* a, const uint32_t* b) {
    asm volatile(
        "mma.sync.aligned.m16n8k8.row.col.f32.tf32.tf32.f32 "
        "{%0,%1,%2,%3}, {%4,%5,%6,%7}, {%8,%9}, {%0,%1,%2,%3};"
        : "+f"(c[0]), "+f"(c[1]), "+f"(c[2]), "+f"(c[3])
        : "r"(a[0]), "r"(a[1]), "r"(a[2]), "r"(a[3]), "r"(b[0]), "r"(b[1]));
}

// ============================================================
// Weight transpose: g_Wt[z][n][k] = W_z[k][n]
// ============================================================
__global__ void wt_kernel(const float* __restrict__ Wq, const float* __restrict__ Wk,
                          const float* __restrict__ Wv, const float* __restrict__ Wo)
{
    __shared__ float t[32][33];
    const int z = blockIdx.z;
    const float* W = (z == 0) ? Wq : (z == 1) ? Wk : (z == 2) ? Wv : Wo;
    const int tx = threadIdx.x, ty = threadIdx.y;
    const int nx = blockIdx.x*32 + tx;
    const int ky = blockIdx.y*32 + ty;
#pragma unroll
    for (int i = 0; i < 32; i += 8)
        t[ty + i][tx] = W[(size_t)(ky + i)*DM + nx];
    __syncthreads();
    const int ok = blockIdx.y*32 + tx;
    const int on = blockIdx.x*32 + ty;
#pragma unroll
    for (int i = 0; i < 32; i += 8)
        g_Wt[z][(size_t)(on + i)*DM + ok] = t[tx][ty + i];
}

// ============================================================
// Memory-slot fill: rows 1024..1087 of g_K/g_V (tf32-rounded)
// ============================================================
__global__ void memfill_kernel(const float* __restrict__ memK,
                               const float* __restrict__ memV)
{
    const int bh = blockIdx.x;
    const int h = bh & 7;
    const float sk = 8.0f;
    const float sv = 6.3245553203367587f;
    for (int idx = threadIdx.x; idx < 64*64; idx += blockDim.x) {
        const int m = idx >> 6;
        const int d = idx & 63;
        float kv = 0.f, vv = 0.f;
        if (m < NM) {
            kv = __uint_as_float(f2tf32(sk * memK[m*DM + h*DKH + d]));
            vv = __uint_as_float(f2tf32(sv * memV[m*DM + h*DKH + d]));
        }
        const size_t o = ((size_t)bh*NKP + 1024 + m)*DKH + d;
        g_K[o] = kv;
        g_V[o] = vv;
    }
}

// ============================================================
// mma.sync tf32 GEMM, double-buffered SMEM, 1 sync/iter.
// Block 128x128, BK=32, 256 threads.
// MODE 0: ->g_Q  1: ->g_K(tf32)  2: ->g_V(tf32)  3: A=g_O,+resid->g_X
// ============================================================
#define KPAD 36
#define GBUF (128*KPAD)
#define GEMM_SMEM (4*GBUF*4)   // 2 arrays x 2 buffers

template<int MODE>
__global__ void __launch_bounds__(256, 2) gemm_mma(const float* __restrict__ A,
                                                   int widx,
                                                   const float* __restrict__ bias,
                                                   const float* __restrict__ resid)
{
    extern __shared__ float gsm[];
    float* Asm = gsm;              // [2][GBUF]
    float* Bsm = gsm + 2*GBUF;     // [2][GBUF]

    const int tid = threadIdx.x;
    const int lane = tid & 31, wid = tid >> 5;
    const int wm = (wid & 1) << 6;
    const int wn = (wid >> 1) << 5;
    const int gr = lane >> 2, tc = lane & 3;
    const int m0 = blockIdx.y << 7, n0 = blockIdx.x << 7;

    const float* Ap = (MODE == 3) ? (const float*)g_O : A;
    const float* Wt = g_Wt[widx];

    const int lrow = tid >> 1;
    const int lcol = (tid & 1) << 4;

    const float* Ag = Ap + (size_t)(m0 + lrow)*DM + lcol;
    const float* Bg = Wt + (size_t)(n0 + lrow)*DM + lcol;

    float acc[4][4][4];
#pragma unroll
    for (int i = 0; i < 4; i++)
#pragma unroll
        for (int j = 0; j < 4; j++)
#pragma unroll
            for (int r = 0; r < 4; r++) acc[i][j][r] = 0.f;

    float4 av[4], bv[4];
#pragma unroll
    for (int u = 0; u < 4; u++) {
        av[u] = *(const float4*)(Ag + 4*u);
        bv[u] = *(const float4*)(Bg + 4*u);
    }

    for (int it = 0; it < 16; it++) {
        const int cur = it & 1;
        float* as_st = Asm + cur*GBUF + lrow*KPAD + lcol;
        float* bs_st = Bsm + cur*GBUF + lrow*KPAD + lcol;
#pragma unroll
        for (int u = 0; u < 4; u++) {
            uint32_t* d = (uint32_t*)(as_st + 4*u);
            d[0] = f2tf32(av[u].x); d[1] = f2tf32(av[u].y);
            d[2] = f2tf32(av[u].z); d[3] = f2tf32(av[u].w);
            uint32_t* e = (uint32_t*)(bs_st + 4*u);
            e[0] = f2tf32(bv[u].x); e[1] = f2tf32(bv[u].y);
            e[2] = f2tf32(bv[u].z); e[3] = f2tf32(bv[u].w);
        }
        __syncthreads();
        if (it < 15) {
            const int kb = (it + 1)*32;
#pragma unroll
            for (int u = 0; u < 4; u++) {
                av[u] = *(const float4*)(Ag + kb + 4*u);
                bv[u] = *(const float4*)(Bg + kb + 4*u);
            }
        }
        const uint32_t* Asu = (const uint32_t*)(Asm + cur*GBUF);
        const uint32_t* Bsu = (const uint32_t*)(Bsm + cur*GBUF);
#pragma unroll
        for (int ks = 0; ks < 32; ks += 8) {
            uint32_t a[4][4], b[4][2];
#pragma unroll
            for (int i = 0; i < 4; i++) {
                const int r0 = (wm + i*16 + gr)*KPAD + ks + tc;
                a[i][0] = Asu[r0];
                a[i][1] = Asu[r0 + 8*KPAD];
                a[i][2] = Asu[r0 + 4];
                a[i][3] = Asu[r0 + 8*KPAD + 4];
            }
#pragma unroll
            for (int j = 0; j < 4; j++) {
                const int r0 = (wn + j*8 + gr)*KPAD + ks + tc;
                b[j][0] = Bsu[r0];
                b[j][1] = Bsu[r0 + 4];
            }
#pragma unroll
            for (int i = 0; i < 4; i++)
#pragma unroll
                for (int j = 0; j < 4; j++)
                    mma_tf32(acc[i][j], a[i], b[j]);
        }
    }

#pragma unroll
    for (int i = 0; i < 4; i++) {
        const int mA = m0 + wm + i*16 + gr;
        const int mB = mA + 8;
#pragma unroll
        for (int j = 0; j < 4; j++) {
            const int n = n0 + wn + j*8 + 2*tc;
            const float b0 = bias[n], b1 = bias[n+1];
            float2 vA = make_float2(acc[i][j][0] + b0, acc[i][j][1] + b1);
            float2 vB = make_float2(acc[i][j][2] + b0, acc[i][j][3] + b1);
            if (MODE == 1 || MODE == 2) {
                vA.x = __uint_as_float(f2tf32(vA.x));
                vA.y = __uint_as_float(f2tf32(vA.y));
                vB.x = __uint_as_float(f2tf32(vB.x));
                vB.y = __uint_as_float(f2tf32(vB.y));
            }
            if (MODE == 3) {
                const float2 rA = *(const float2*)(resid + (size_t)mA*DM + n);
                const float2 rB = *(const float2*)(resid + (size_t)mB*DM + n);
                vA.x += rA.x; vA.y += rA.y;
                vB.x += rB.x; vB.y += rB.y;
                *(float2*)(&g_X[(size_t)mA*DM + n]) = vA;
                *(float2*)(&g_X[(size_t)mB*DM + n]) = vB;
            } else {
                const int h = n >> 6, d = n & 63;
                const int bbA = mA >> 10, nnA = mA & 1023;
                const int bbB = mB >> 10, nnB = mB & 1023;
                if (MODE == 0) {
                    *(float2*)(&g_Q[(((size_t)bbA*NH + h)*NQ + nnA)*DKH + d]) = vA;
                    *(float2*)(&g_Q[(((size_t)bbB*NH + h)*NQ + nnB)*DKH + d]) = vB;
                } else if (MODE == 1) {
                    *(float2*)(&g_K[(((size_t)bbA*NH + h)*NKP + nnA)*DKH + d]) = vA;
                    *(float2*)(&g_K[(((size_t)bbB*NH + h)*NKP + nnB)*DKH + d]) = vB;
                } else {
                    *(float2*)(&g_V[(((size_t)bbA*NH + h)*NKP + nnA)*DKH + d]) = vA;
                    *(float2*)(&g_V[(((size_t)bbB*NH + h)*NKP + nnB)*DKH + d]) = vB;
                }
            }
        }
    }
}

// ============================================================
// Tensor-core flash attention, double-buffered K/V (1 sync/tile),
// log2-domain softmax (ex2.approx), K/V staged as raw tf32 bits.
// Block = one (b,h) x 64 queries, 4 warps.
// ============================================================
#define ASTRIDE 68
#define KVSZ (64*ASTRIDE)
#define ATT2_SMEM (5*KVSZ*4)

__global__ void __launch_bounds__(128) attn_mma_kernel(const float* __restrict__ AW)
{
    extern __shared__ uint32_t dsm[];
    // layout: K0 @0, V0 @KVSZ, K1 @2*KVSZ, V1 @3*KVSZ, Ps @4*KVSZ
    uint32_t* Ps = dsm + 4*KVSZ;

    const int tid = threadIdx.x, lane = tid & 31, wid = tid >> 5;
    const int bh = blockIdx.y, b = bh >> 3, h = bh & 7;
    const int q0 = blockIdx.x << 6;
    const int gr = lane >> 2, tc = lane & 3;
    const int qw = wid << 4;
    const float QSC = 0.125f * 1.4426950408889634f;   // 1/sqrt(dk) * log2(e)

    // ---- stage Q (scaled into log2 domain, tf32) ----
    {
        const int r = tid >> 1, c0 = (tid & 1) << 5;
        const float* qp = g_Q + ((size_t)bh*NQ + q0 + r)*DKH + c0;
#pragma unroll
        for (int u = 0; u < 8; u++) {
            const float4 t = *(const float4*)(qp + 4*u);
            uint4 w;
            w.x = f2tf32(QSC*t.x); w.y = f2tf32(QSC*t.y);
            w.z = f2tf32(QSC*t.z); w.w = f2tf32(QSC*t.w);
            *(uint4*)(&Ps[r*ASTRIDE + c0 + 4*u]) = w;
        }
    }
    __syncthreads();

    uint32_t qf[8][4];
#pragma unroll
    for (int ks = 0; ks < 8; ks++) {
        const int r0 = (qw + gr)*ASTRIDE + ks*8 + tc;
        qf[ks][0] = Ps[r0];
        qf[ks][1] = Ps[r0 + 8*ASTRIDE];
        qf[ks][2] = Ps[r0 + 4];
        qf[ks][3] = Ps[r0 + 8*ASTRIDE + 4];
    }

    // ---- K/V staging config (raw bit copies; producer already tf32) ----
    const int rr = tid >> 1;             // row 0..63
    const int cc = (tid & 1) << 5;       // col 0 or 32
    const uint4* kg = (const uint4*)(g_K + ((size_t)bh*NKP + rr)*DKH + cc);
    const uint4* vg = (const uint4*)(g_V + ((size_t)bh*NKP + rr)*DKH + cc);
    const int gstep = 64*DKH/4;          // uint4 stride per kv tile

    uint4 kr[8], vr[8];
#pragma unroll
    for (int u = 0; u < 8; u++) { kr[u] = kg[u]; vr[u] = vg[u]; }

    // write tile 0 into buffer 0
    {
        uint32_t* kd = dsm + rr*ASTRIDE + cc;
        uint32_t* vd = dsm + KVSZ + rr*ASTRIDE + cc;
#pragma unroll
        for (int u = 0; u < 8; u++) {
            *(uint4*)(kd + 4*u) = kr[u];
            *(uint4*)(vd + 4*u) = vr[u];
        }
    }
    __syncthreads();

    float o[8][4];
#pragma unroll
    for (int j = 0; j < 8; j++)
#pragma unroll
        for (int r = 0; r < 4; r++) o[j][r] = 0.f;
    float m0 = -1e30f, m1 = -1e30f, l0 = 0.f, l1 = 0.f;

    for (int kt = 0; kt < 17; kt++) {
        const uint32_t* Ks = dsm + (kt & 1)*2*KVSZ;
        const uint32_t* Vs = Ks + KVSZ;

        // prefetch next tile (hidden under compute below)
        if (kt < 16) {
#pragma unroll
            for (int u = 0; u < 8; u++) {
                kr[u] = kg[(kt+1)*gstep + u];
                vr[u] = vg[(kt+1)*gstep + u];
            }
        }

        // ---- S = Qs @ K^T (log2 domain) ----
        float sc[8][4];
#pragma unroll
        for (int j = 0; j < 8; j++) {
            sc[j][0] = sc[j][1] = sc[j][2] = sc[j][3] = 0.f;
#pragma unroll
            for (int ks = 0; ks < 8; ks++) {
                uint32_t bb[2];
                const int r0 = (j*8 + gr)*ASTRIDE + ks*8 + tc;
                bb[0] = Ks[r0];
                bb[1] = Ks[r0 + 4];
                mma_tf32(sc[j], qf[ks], bb);
            }
        }

        // ---- attention_weights / memory mask ----
        if (kt < 16) {
            const float* aw0 = AW + ((size_t)b*NQ + q0 + qw + gr)*NKK + kt*64 + 2*tc;
            const float* aw1 = aw0 + 8*(size_t)NKK;
#pragma unroll
            for (int j = 0; j < 8; j++) {
                const float2 w0 = *(const float2*)(aw0 + j*8);
                const float2 w1 = *(const float2*)(aw1 + j*8);
                sc[j][0] *= w0.x; sc[j][1] *= w0.y;
                sc[j][2] *= w1.x; sc[j][3] *= w1.y;
            }
        } else {
#pragma unroll
            for (int j = 0; j < 8; j++) {
                const int c = j*8 + 2*tc;
                if (c >= NM)     { sc[j][0] = -1e30f; sc[j][2] = -1e30f; }
                if (c + 1 >= NM) { sc[j][1] = -1e30f; sc[j][3] = -1e30f; }
            }
        }

        // ---- online softmax (base-2) ----
        float rm0 = -1e30f, rm1 = -1e30f;
#pragma unroll
        for (int j = 0; j < 8; j++) {
            rm0 = fmaxf(rm0, fmaxf(sc[j][0], sc[j][1]));
            rm1 = fmaxf(rm1, fmaxf(sc[j][2], sc[j][3]));
        }
        rm0 = fmaxf(rm0, __shfl_xor_sync(0xffffffffu, rm0, 1));
        rm0 = fmaxf(rm0, __shfl_xor_sync(0xffffffffu, rm0, 2));
        rm1 = fmaxf(rm1, __shfl_xor_sync(0xffffffffu, rm1, 1));
        rm1 = fmaxf(rm1, __shfl_xor_sync(0xffffffffu, rm1, 2));
        const float mn0 = fmaxf(m0, rm0), mn1 = fmaxf(m1, rm1);
        const float c0 = ex2f(m0 - mn0), c1 = ex2f(m1 - mn1);
        m0 = mn0; m1 = mn1;

        float s0 = 0.f, s1 = 0.f;
        uint32_t* pr0 = &Ps[(qw + gr)*ASTRIDE + 2*tc];
        uint32_t* pr1 = pr0 + 8*ASTRIDE;
#pragma unroll
        for (int j = 0; j < 8; j++) {
            const float p00 = ex2f(sc[j][0] - mn0);
            const float p01 = ex2f(sc[j][1] - mn0);
            const float p10 = ex2f(sc[j][2] - mn1);
            const float p11 = ex2f(sc[j][3] - mn1);
            s0 += p00 + p01;
            s1 += p10 + p11;
            uint2 u0; u0.x = f2tf32(p00); u0.y = f2tf32(p01);
            uint2 u1; u1.x = f2tf32(p10); u1.y = f2tf32(p11);
            *(uint2*)(pr0 + j*8) = u0;
            *(uint2*)(pr1 + j*8) = u1;
        }
        s0 += __shfl_xor_sync(0xffffffffu, s0, 1);
        s0 += __shfl_xor_sync(0xffffffffu, s0, 2);
        s1 += __shfl_xor_sync(0xffffffffu, s1, 1);
        s1 += __shfl_xor_sync(0xffffffffu, s1, 2);
        l0 = l0*c0 + s0;
        l1 = l1*c1 + s1;
#pragma unroll
        for (int j = 0; j < 8; j++) {
            o[j][0] *= c0; o[j][1] *= c0;
            o[j][2] *= c1; o[j][3] *= c1;
        }
        __syncwarp();   // P rows are warp-private

        // ---- O += P @ V ----
#pragma unroll
        for (int ks = 0; ks < 8; ks++) {
            uint32_t a[4];
            const int r0 = (qw + gr)*ASTRIDE + ks*8 + tc;
            a[0] = Ps[r0];
            a[1] = Ps[r0 + 8*ASTRIDE];
            a[2] = Ps[r0 + 4];
            a[3] = Ps[r0 + 8*ASTRIDE + 4];
#pragma unroll
            for (int j = 0; j < 8; j++) {
                uint32_t bb[2];
                bb[0] = Vs[(ks*8 + tc)*ASTRIDE + j*8 + gr];
                bb[1] = Vs[(ks*8 + tc + 4)*ASTRIDE + j*8 + gr];
                mma_tf32(o[j], a, bb);
            }
        }

        // ---- store prefetched tile into the other buffer ----
        if (kt < 16) {
            uint32_t* kd = dsm + ((kt+1) & 1)*2*KVSZ + rr*ASTRIDE + cc;
            uint32_t* vd = kd + KVSZ;
#pragma unroll
            for (int u = 0; u < 8; u++) {
                *(uint4*)(kd + 4*u) = kr[u];
                *(uint4*)(vd + 4*u) = vr[u];
            }
            __syncthreads();
        }
    }

    // ---- normalize + write ----
    const float inv0 = 1.0f / l0, inv1 = 1.0f / l1;
    float* op0 = g_O + ((size_t)b*NQ + q0 + qw + gr)*DM + h*DKH + 2*tc;
    float* op1 = op0 + 8*(size_t)DM;
#pragma unroll
    for (int j = 0; j < 8; j++) {
        *(float2*)(op0 + j*8) = make_float2(o[j][0]*inv0, o[j][1]*inv0);
        *(float2*)(op1 + j*8) = make_float2(o[j][2]*inv1, o[j][3]*inv1);
    }
}

// ============================================================
// LayerNorm: warp per row (512 elems), eps=1e-3
// ============================================================
__global__ void __launch_bounds__(256) ln_kernel(const float* __restrict__ gamma,
                                                 const float* __restrict__ beta,
                                                 float* __restrict__ out)
{
    const int row = blockIdx.x*8 + (threadIdx.x >> 5);
    const int lane = threadIdx.x & 31;
    const float* xr = g_X + (size_t)row*DM;
    float v[16];
    float s = 0.f, s2 = 0.f;
#pragma unroll
    for (int u = 0; u < 4; u++) {
        const float4 t = *(const float4*)(xr + lane*4 + u*128);
        v[4*u+0] = t.x; v[4*u+1] = t.y; v[4*u+2] = t.z; v[4*u+3] = t.w;
        s  += t.x + t.y + t.z + t.w;
        s2 += t.x*t.x + t.y*t.y + t.z*t.z + t.w*t.w;
    }
#pragma unroll
    for (int off = 16; off > 0; off >>= 1) {
        s  += __shfl_xor_sync(0xffffffffu, s,  off);
        s2 += __shfl_xor_sync(0xffffffffu, s2, off);
    }
    const float mu  = s * (1.f/512.f);
    const float var = s2 * (1.f/512.f) - mu*mu;
    const float rs  = rsqrtf(var + 1e-3f);
    float* orow = out + (size_t)row*DM;
#pragma unroll
    for (int u = 0; u < 4; u++) {
        const int d = lane*4 + u*128;
        const float4 g  = *(const float4*)(gamma + d);
        const float4 bt = *(const float4*)(beta + d);
        float4 r;
        r.x = g.x*(v[4*u+0]-mu)*rs + bt.x;
        r.y = g.y*(v[4*u+1]-mu)*rs + bt.y;
        r.z = g.z*(v[4*u+2]-mu)*rs + bt.z;
        r.w = g.w*(v[4*u+3]-mu)*rs + bt.w;
        *(float4*)(orow + d) = r;
    }
}

// ============================================================
extern "C" void kernel_launch(void* const* d_in, const int* in_sizes, int n_in,
                              void* d_out, int out_size)
{
    (void)in_sizes; (void)n_in; (void)out_size;
    const float* queries = (const float*)d_in[0];
    const float* keys    = (const float*)d_in[1];
    const float* values  = (const float*)d_in[2];
    const float* aw      = (const float*)d_in[3];
    const float* bq = (const float*)d_in[5];
    const float* bk = (const float*)d_in[7];
    const float* bv = (const float*)d_in[9];
    const float* bo = (const float*)d_in[11];
    const float* memK = (const float*)d_in[12];
    const float* memV = (const float*)d_in[13];
    const float* gamma = (const float*)d_in[14];
    const float* beta  = (const float*)d_in[15];
    float* out = (float*)d_out;

    cudaFuncSetAttribute(attn_mma_kernel,
                         cudaFuncAttributeMaxDynamicSharedMemorySize, ATT2_SMEM);
    cudaFuncSetAttribute(gemm_mma<0>, cudaFuncAttributeMaxDynamicSharedMemorySize, GEMM_SMEM);
    cudaFuncSetAttribute(gemm_mma<1>, cudaFuncAttributeMaxDynamicSharedMemorySize, GEMM_SMEM);
    cudaFuncSetAttribute(gemm_mma<2>, cudaFuncAttributeMaxDynamicSharedMemorySize, GEMM_SMEM);
    cudaFuncSetAttribute(gemm_mma<3>, cudaFuncAttributeMaxDynamicSharedMemorySize, GEMM_SMEM);

    const dim3 gg(4, 128);
    wt_kernel<<<dim3(16, 16, 4), dim3(32, 8)>>>(
        (const float*)d_in[4], (const float*)d_in[6],
        (const float*)d_in[8], (const float*)d_in[10]);
    memfill_kernel<<<128, 256>>>(memK, memV);
    gemm_mma<0><<<gg, 256, GEMM_SMEM>>>(queries, 0, bq, nullptr);
    gemm_mma<1><<<gg, 256, GEMM_SMEM>>>(keys,    1, bk, nullptr);
    gemm_mma<2><<<gg, 256, GEMM_SMEM>>>(values,  2, bv, nullptr);
    attn_mma_kernel<<<dim3(16, 128), 128, ATT2_SMEM>>>(aw);
    gemm_mma<3><<<gg, 256, GEMM_SMEM>>>(nullptr, 3, bo, queries);
    ln_kernel<<<ROWS/8, 256>>>(gamma, beta, out);
}

// round 6
// speedup vs baseline: 1.4625x; 1.4625x over previous
#include <cuda_runtime.h>
#include <cstdint>
#include <math.h>

// Problem constants
#define NB 16
#define NQ 1024
#define NKK 1024
#define DM 512
#define NH 8
#define DKH 64
#define NM 40
#define NKP 1088          // padded key length: 17 * 64
#define ROWS (NB*NQ)      // 16384

// -------- scratch (static device memory: allowed) --------
__device__ float g_Q[(size_t)NB*NH*NQ*DKH];     // [bh][1024][64] fp32
__device__ float g_K[(size_t)NB*NH*NKP*DKH];    // [bh][1088][64] fp32
__device__ float g_V[(size_t)NB*NH*NKP*DKH];    // [bh][1088][64] fp32
__device__ float g_O[(size_t)ROWS*DM];          // attention out
__device__ float g_X[(size_t)ROWS*DM];          // proj + residual
__device__ float g_Wt[4][(size_t)DM*DM];        // transposed weights [n][k]

// ============================================================
// helpers (base ISA: mma.sync bf16 m16n8k16 + ldmatrix)
// ============================================================
__device__ __forceinline__ uint32_t smem_u32(const void* p) {
    uint32_t a;
    asm("{ .reg .u64 t; cvta.to.shared.u64 t, %1; cvt.u32.u64 %0, t; }"
        : "=r"(a) : "l"(p));
    return a;
}
__device__ __forceinline__ uint32_t pk2(float lo, float hi) {  // {lo,hi} bf16x2
    uint32_t r;
    asm("cvt.rn.bf16x2.f32 %0, %1, %2;" : "=r"(r) : "f"(hi), "f"(lo));
    return r;
}
__device__ __forceinline__ float ex2f(float x) {
    float y;
    asm("ex2.approx.f32 %0, %1;" : "=f"(y) : "f"(x));
    return y;
}
__device__ __forceinline__ void mma_bf16(float* c, const uint32_t* a, const uint32_t* b) {
    asm volatile(
        "mma.sync.aligned.m16n8k16.row.col.f32.bf16.bf16.f32 "
        "{%0,%1,%2,%3}, {%4,%5,%6,%7}, {%8,%9}, {%0,%1,%2,%3};"
        : "+f"(c[0]), "+f"(c[1]), "+f"(c[2]), "+f"(c[3])
        : "r"(a[0]), "r"(a[1]), "r"(a[2]), "r"(a[3]), "r"(b[0]), "r"(b[1]));
}
__device__ __forceinline__ void ldsm4(uint32_t* r, uint32_t addr) {
    asm volatile("ldmatrix.sync.aligned.m8n8.x4.shared.b16 {%0,%1,%2,%3}, [%4];"
                 : "=r"(r[0]), "=r"(r[1]), "=r"(r[2]), "=r"(r[3]) : "r"(addr));
}
__device__ __forceinline__ void ldsm4t(uint32_t* r, uint32_t addr) {
    asm volatile("ldmatrix.sync.aligned.m8n8.x4.trans.shared.b16 {%0,%1,%2,%3}, [%4];"
                 : "=r"(r[0]), "=r"(r[1]), "=r"(r[2]), "=r"(r[3]) : "r"(addr));
}

// ============================================================
// Weight transpose: g_Wt[z][n][k] = W_z[k][n]
// ============================================================
__global__ void wt_kernel(const float* __restrict__ Wq, const float* __restrict__ Wk,
                          const float* __restrict__ Wv, const float* __restrict__ Wo)
{
    __shared__ float t[32][33];
    const int z = blockIdx.z;
    const float* W = (z == 0) ? Wq : (z == 1) ? Wk : (z == 2) ? Wv : Wo;
    const int tx = threadIdx.x, ty = threadIdx.y;
    const int nx = blockIdx.x*32 + tx;
    const int ky = blockIdx.y*32 + ty;
#pragma unroll
    for (int i = 0; i < 32; i += 8)
        t[ty + i][tx] = W[(size_t)(ky + i)*DM + nx];
    __syncthreads();
    const int ok = blockIdx.y*32 + tx;
    const int on = blockIdx.x*32 + ty;
#pragma unroll
    for (int i = 0; i < 32; i += 8)
        g_Wt[z][(size_t)(on + i)*DM + ok] = t[tx][ty + i];
}

// ============================================================
// Memory-slot fill: rows 1024..1087 of g_K/g_V
// ============================================================
__global__ void memfill_kernel(const float* __restrict__ memK,
                               const float* __restrict__ memV)
{
    const int bh = blockIdx.x;
    const int h = bh & 7;
    const float sk = 8.0f;
    const float sv = 6.3245553203367587f;
    for (int idx = threadIdx.x; idx < 64*64; idx += blockDim.x) {
        const int m = idx >> 6;
        const int d = idx & 63;
        float kv = 0.f, vv = 0.f;
        if (m < NM) {
            kv = sk * memK[m*DM + h*DKH + d];
            vv = sv * memV[m*DM + h*DKH + d];
        }
        const size_t o = ((size_t)bh*NKP + 1024 + m)*DKH + d;
        g_K[o] = kv;
        g_V[o] = vv;
    }
}

// ============================================================
// bf16 mma GEMM: C[16384,512] = A @ Wt^T + bias
// Block 128x128, BK=32, 256 threads (8 warps, warp tile 64x32).
// Double-buffered bf16 SMEM (1 sync/iter), ldmatrix fragments.
// Row stride 40 bf16 (80 B) -> LDSM phases hit all 32 banks.
// ============================================================
#define GROWB 80                   // bytes per SMEM row (32 bf16 + pad)
#define GBUFB (128*GROWB)          // 10240 B per tile buffer
#define GEMM_SMEM (4*GBUFB)        // A0,A1,B0,B1 = 40960 B

template<int MODE>
__global__ void __launch_bounds__(256, 2) gemm_bf16(const float* __restrict__ A,
                                                    int widx,
                                                    const float* __restrict__ bias,
                                                    const float* __restrict__ resid)
{
    extern __shared__ char gsm[];
    const uint32_t sbase = smem_u32(gsm);

    const int tid = threadIdx.x;
    const int lane = tid & 31, wid = tid >> 5;
    const int wm = (wid & 1) << 6;
    const int wn = (wid >> 1) << 5;
    const int gr = lane >> 2, tc = lane & 3;
    const int m0 = blockIdx.y << 7, n0 = blockIdx.x << 7;

    const float* Ap = (MODE == 3) ? (const float*)g_O : A;
    const float* Wt = g_Wt[widx];

    const int lrow = tid >> 1;              // 0..127
    const int lseg = tid & 1;               // half-row (16 floats)
    const float* Ag = Ap + (size_t)(m0 + lrow)*DM + lseg*16;
    const float* Bg = Wt + (size_t)(n0 + lrow)*DM + lseg*16;
    const uint32_t a_st = sbase + lrow*GROWB + lseg*32;
    const uint32_t b_st = a_st + 2*GBUFB;

    // fragment LDSM base addresses
    const int lr16 = lane & 15, lk8 = lane >> 4;
    const uint32_t a_ld = sbase + (wm + lr16)*GROWB + lk8*16;
    const uint32_t b_ld = sbase + 2*GBUFB + (wn + lr16)*GROWB + lk8*16;

    float acc[4][4][4];
#pragma unroll
    for (int i = 0; i < 4; i++)
#pragma unroll
        for (int j = 0; j < 4; j++)
#pragma unroll
            for (int r = 0; r < 4; r++) acc[i][j][r] = 0.f;

    float4 av[4], bv[4];
#pragma unroll
    for (int u = 0; u < 4; u++) {
        av[u] = *(const float4*)(Ag + 4*u);
        bv[u] = *(const float4*)(Bg + 4*u);
    }

    for (int it = 0; it < 16; it++) {
        const uint32_t bufo = (uint32_t)(it & 1)*GBUFB;
        // STS (fp32 -> bf16 pack, two 16B stores per array)
        {
            uint32_t p0 = pk2(av[0].x, av[0].y), p1 = pk2(av[0].z, av[0].w);
            uint32_t p2 = pk2(av[1].x, av[1].y), p3 = pk2(av[1].z, av[1].w);
            asm volatile("st.shared.v4.b32 [%0], {%1,%2,%3,%4};"
                         :: "r"(a_st + bufo), "r"(p0), "r"(p1), "r"(p2), "r"(p3));
            p0 = pk2(av[2].x, av[2].y); p1 = pk2(av[2].z, av[2].w);
            p2 = pk2(av[3].x, av[3].y); p3 = pk2(av[3].z, av[3].w);
            asm volatile("st.shared.v4.b32 [%0], {%1,%2,%3,%4};"
                         :: "r"(a_st + bufo + 16), "r"(p0), "r"(p1), "r"(p2), "r"(p3));
            p0 = pk2(bv[0].x, bv[0].y); p1 = pk2(bv[0].z, bv[0].w);
            p2 = pk2(bv[1].x, bv[1].y); p3 = pk2(bv[1].z, bv[1].w);
            asm volatile("st.shared.v4.b32 [%0], {%1,%2,%3,%4};"
                         :: "r"(b_st + bufo), "r"(p0), "r"(p1), "r"(p2), "r"(p3));
            p0 = pk2(bv[2].x, bv[2].y); p1 = pk2(bv[2].z, bv[2].w);
            p2 = pk2(bv[3].x, bv[3].y); p3 = pk2(bv[3].z, bv[3].w);
            asm volatile("st.shared.v4.b32 [%0], {%1,%2,%3,%4};"
                         :: "r"(b_st + bufo + 16), "r"(p0), "r"(p1), "r"(p2), "r"(p3));
        }
        __syncthreads();
        if (it < 15) {
            const int kb = (it + 1)*32;
#pragma unroll
            for (int u = 0; u < 4; u++) {
                av[u] = *(const float4*)(Ag + kb + 4*u);
                bv[u] = *(const float4*)(Bg + kb + 4*u);
            }
        }
#pragma unroll
        for (int ks = 0; ks < 2; ks++) {
            uint32_t a[4][4], b[4][2];
#pragma unroll
            for (int i = 0; i < 4; i++)
                ldsm4(a[i], a_ld + bufo + i*16*GROWB + ks*32);
#pragma unroll
            for (int jp = 0; jp < 2; jp++) {
                uint32_t t[4];
                ldsm4(t, b_ld + bufo + jp*16*GROWB + ks*32);
                b[2*jp][0]   = t[0]; b[2*jp+1][0] = t[1];
                b[2*jp][1]   = t[2]; b[2*jp+1][1] = t[3];
            }
#pragma unroll
            for (int i = 0; i < 4; i++)
#pragma unroll
                for (int j = 0; j < 4; j++)
                    mma_bf16(acc[i][j], a[i], b[j]);
        }
    }

    // epilogue: c0,c1 -> (row gr, cols 2tc,2tc+1); c2,c3 -> row gr+8
#pragma unroll
    for (int i = 0; i < 4; i++) {
        const int mA = m0 + wm + i*16 + gr;
        const int mB = mA + 8;
#pragma unroll
        for (int j = 0; j < 4; j++) {
            const int n = n0 + wn + j*8 + 2*tc;
            const float b0 = bias[n], b1 = bias[n+1];
            float2 vA = make_float2(acc[i][j][0] + b0, acc[i][j][1] + b1);
            float2 vB = make_float2(acc[i][j][2] + b0, acc[i][j][3] + b1);
            if (MODE == 3) {
                const float2 rA = *(const float2*)(resid + (size_t)mA*DM + n);
                const float2 rB = *(const float2*)(resid + (size_t)mB*DM + n);
                vA.x += rA.x; vA.y += rA.y;
                vB.x += rB.x; vB.y += rB.y;
                *(float2*)(&g_X[(size_t)mA*DM + n]) = vA;
                *(float2*)(&g_X[(size_t)mB*DM + n]) = vB;
            } else {
                const int h = n >> 6, d = n & 63;
                const int bbA = mA >> 10, nnA = mA & 1023;
                const int bbB = mB >> 10, nnB = mB & 1023;
                if (MODE == 0) {
                    *(float2*)(&g_Q[(((size_t)bbA*NH + h)*NQ + nnA)*DKH + d]) = vA;
                    *(float2*)(&g_Q[(((size_t)bbB*NH + h)*NQ + nnB)*DKH + d]) = vB;
                } else if (MODE == 1) {
                    *(float2*)(&g_K[(((size_t)bbA*NH + h)*NKP + nnA)*DKH + d]) = vA;
                    *(float2*)(&g_K[(((size_t)bbB*NH + h)*NKP + nnB)*DKH + d]) = vB;
                } else {
                    *(float2*)(&g_V[(((size_t)bbA*NH + h)*NKP + nnA)*DKH + d]) = vA;
                    *(float2*)(&g_V[(((size_t)bbB*NH + h)*NKP + nnB)*DKH + d]) = vB;
                }
            }
        }
    }
}

// ============================================================
// bf16 tensor-core flash attention.
// Block = one (b,h) x 64 queries, 4 warps (16 q-rows each).
// log2-domain softmax (ex2.approx), ldmatrix fragments,
// K/V register prefetch (packed bf16), single KV buffer.
// Row stride 144 B (72 bf16) -> LDSM phases conflict-free.
// ============================================================
#define AROWB 144
#define ATILEB (64*AROWB)          // 9216 B

__global__ void __launch_bounds__(128) attn_mma_kernel(const float* __restrict__ AW)
{
    __shared__ char asm_[3*ATILEB];  // Ks, Vs, Ps(Q staging then P)
    const uint32_t sK = smem_u32(asm_);
    const uint32_t sV = sK + ATILEB;
    const uint32_t sP = sK + 2*ATILEB;

    const int tid = threadIdx.x, lane = tid & 31, wid = tid >> 5;
    const int bh = blockIdx.y, b = bh >> 3, h = bh & 7;
    const int q0 = blockIdx.x << 6;
    const int gr = lane >> 2, tc = lane & 3;
    const int qw = wid << 4;
    const int lr16 = lane & 15, lk8 = lane >> 4;
    const float QSC = 0.125f * 1.4426950408889634f;   // 1/sqrt(dk) * log2(e)

    // ---- stage Q (scaled into log2 domain, bf16) ----
    const int rr = tid >> 1;             // 0..63
    const int cc = (tid & 1) << 5;       // col 0 or 32
    {
        const float* qp = g_Q + ((size_t)bh*NQ + q0 + rr)*DKH + cc;
        const uint32_t qst = sP + rr*AROWB + cc*2;
#pragma unroll
        for (int u = 0; u < 2; u++) {
            const float4 t0 = *(const float4*)(qp + 16*u);
            const float4 t1 = *(const float4*)(qp + 16*u + 4);
            const float4 t2 = *(const float4*)(qp + 16*u + 8);
            const float4 t3 = *(const float4*)(qp + 16*u + 12);
            uint32_t p0 = pk2(QSC*t0.x, QSC*t0.y), p1 = pk2(QSC*t0.z, QSC*t0.w);
            uint32_t p2 = pk2(QSC*t1.x, QSC*t1.y), p3 = pk2(QSC*t1.z, QSC*t1.w);
            asm volatile("st.shared.v4.b32 [%0], {%1,%2,%3,%4};"
                         :: "r"(qst + 32*u), "r"(p0), "r"(p1), "r"(p2), "r"(p3));
            p0 = pk2(QSC*t2.x, QSC*t2.y); p1 = pk2(QSC*t2.z, QSC*t2.w);
            p2 = pk2(QSC*t3.x, QSC*t3.y); p3 = pk2(QSC*t3.z, QSC*t3.w);
            asm volatile("st.shared.v4.b32 [%0], {%1,%2,%3,%4};"
                         :: "r"(qst + 32*u + 16), "r"(p0), "r"(p1), "r"(p2), "r"(p3));
        }
    }
    __syncthreads();

    uint32_t qf[4][4];
#pragma unroll
    for (int ks = 0; ks < 4; ks++)
        ldsm4(qf[ks], sP + (qw + lr16)*AROWB + lk8*16 + ks*32);

    // ---- K/V global pointers + first tile prefetch (packed bf16) ----
    const float* kgp = g_K + ((size_t)bh*NKP + rr)*DKH + cc;
    const float* vgp = g_V + ((size_t)bh*NKP + rr)*DKH + cc;
    const uint32_t kst = sK + rr*AROWB + cc*2;
    const uint32_t vst = sV + rr*AROWB + cc*2;

    uint32_t ku[16], vu[16];
#pragma unroll
    for (int u = 0; u < 8; u++) {
        const float4 t = *(const float4*)(kgp + 4*u);
        ku[2*u] = pk2(t.x, t.y); ku[2*u+1] = pk2(t.z, t.w);
        const float4 v = *(const float4*)(vgp + 4*u);
        vu[2*u] = pk2(v.x, v.y); vu[2*u+1] = pk2(v.z, v.w);
    }

    float o[8][4];
#pragma unroll
    for (int j = 0; j < 8; j++)
#pragma unroll
        for (int r = 0; r < 4; r++) o[j][r] = 0.f;
    float m0 = -1e30f, m1 = -1e30f, l0 = 0.f, l1 = 0.f;

    for (int kt = 0; kt < 17; kt++) {
        if (kt > 0) __syncthreads();   // all warps done reading prev tile
        // STS K/V tile kt
#pragma unroll
        for (int u = 0; u < 4; u++) {
            asm volatile("st.shared.v4.b32 [%0], {%1,%2,%3,%4};"
                         :: "r"(kst + 16*u), "r"(ku[4*u]), "r"(ku[4*u+1]),
                            "r"(ku[4*u+2]), "r"(ku[4*u+3]));
            asm volatile("st.shared.v4.b32 [%0], {%1,%2,%3,%4};"
                         :: "r"(vst + 16*u), "r"(vu[4*u]), "r"(vu[4*u+1]),
                            "r"(vu[4*u+2]), "r"(vu[4*u+3]));
        }
        __syncthreads();

        // prefetch next tile (hidden under compute below)
        if (kt < 16) {
            const float* kn = kgp + (size_t)(kt+1)*64*DKH;
            const float* vn = vgp + (size_t)(kt+1)*64*DKH;
#pragma unroll
            for (int u = 0; u < 8; u++) {
                const float4 t = *(const float4*)(kn + 4*u);
                ku[2*u] = pk2(t.x, t.y); ku[2*u+1] = pk2(t.z, t.w);
                const float4 v = *(const float4*)(vn + 4*u);
                vu[2*u] = pk2(v.x, v.y); vu[2*u+1] = pk2(v.z, v.w);
            }
        }

        // ---- S = Qs @ K^T (log2 domain) ----
        float sc[8][4];
#pragma unroll
        for (int j = 0; j < 8; j++)
            sc[j][0] = sc[j][1] = sc[j][2] = sc[j][3] = 0.f;
#pragma unroll
        for (int ks = 0; ks < 4; ks++) {
#pragma unroll
            for (int jp = 0; jp < 4; jp++) {
                uint32_t t[4];
                ldsm4(t, sK + (jp*16 + lr16)*AROWB + lk8*16 + ks*32);
                uint32_t b0[2] = {t[0], t[2]};
                uint32_t b1[2] = {t[1], t[3]};
                mma_bf16(sc[2*jp],   qf[ks], b0);
                mma_bf16(sc[2*jp+1], qf[ks], b1);
            }
        }

        // ---- attention_weights / memory mask ----
        if (kt < 16) {
            const float* aw0 = AW + ((size_t)b*NQ + q0 + qw + gr)*NKK + kt*64 + 2*tc;
            const float* aw1 = aw0 + 8*(size_t)NKK;
#pragma unroll
            for (int j = 0; j < 8; j++) {
                const float2 w0 = *(const float2*)(aw0 + j*8);
                const float2 w1 = *(const float2*)(aw1 + j*8);
                sc[j][0] *= w0.x; sc[j][1] *= w0.y;
                sc[j][2] *= w1.x; sc[j][3] *= w1.y;
            }
        } else {
#pragma unroll
            for (int j = 0; j < 8; j++) {
                const int c = j*8 + 2*tc;
                if (c >= NM)     { sc[j][0] = -1e30f; sc[j][2] = -1e30f; }
                if (c + 1 >= NM) { sc[j][1] = -1e30f; sc[j][3] = -1e30f; }
            }
        }

        // ---- online softmax (base-2) ----
        float rm0 = -1e30f, rm1 = -1e30f;
#pragma unroll
        for (int j = 0; j < 8; j++) {
            rm0 = fmaxf(rm0, fmaxf(sc[j][0], sc[j][1]));
            rm1 = fmaxf(rm1, fmaxf(sc[j][2], sc[j][3]));
        }
        rm0 = fmaxf(rm0, __shfl_xor_sync(0xffffffffu, rm0, 1));
        rm0 = fmaxf(rm0, __shfl_xor_sync(0xffffffffu, rm0, 2));
        rm1 = fmaxf(rm1, __shfl_xor_sync(0xffffffffu, rm1, 1));
        rm1 = fmaxf(rm1, __shfl_xor_sync(0xffffffffu, rm1, 2));
        const float mn0 = fmaxf(m0, rm0), mn1 = fmaxf(m1, rm1);
        const float c0 = ex2f(m0 - mn0), c1 = ex2f(m1 - mn1);
        m0 = mn0; m1 = mn1;

        float s0 = 0.f, s1 = 0.f;
        const uint32_t pr0 = sP + (qw + gr)*AROWB + 4*tc;
        const uint32_t pr1 = pr0 + 8*AROWB;
#pragma unroll
        for (int j = 0; j < 8; j++) {
            const float p00 = ex2f(sc[j][0] - mn0);
            const float p01 = ex2f(sc[j][1] - mn0);
            const float p10 = ex2f(sc[j][2] - mn1);
            const float p11 = ex2f(sc[j][3] - mn1);
            s0 += p00 + p01;
            s1 += p10 + p11;
            const uint32_t u0 = pk2(p00, p01);
            const uint32_t u1 = pk2(p10, p11);
            asm volatile("st.shared.b32 [%0], %1;" :: "r"(pr0 + j*16), "r"(u0));
            asm volatile("st.shared.b32 [%0], %1;" :: "r"(pr1 + j*16), "r"(u1));
        }
        s0 += __shfl_xor_sync(0xffffffffu, s0, 1);
        s0 += __shfl_xor_sync(0xffffffffu, s0, 2);
        s1 += __shfl_xor_sync(0xffffffffu, s1, 1);
        s1 += __shfl_xor_sync(0xffffffffu, s1, 2);
        l0 = l0*c0 + s0;
        l1 = l1*c1 + s1;
#pragma unroll
        for (int j = 0; j < 8; j++) {
            o[j][0] *= c0; o[j][1] *= c0;
            o[j][2] *= c1; o[j][3] *= c1;
        }
        __syncwarp();   // P rows are warp-private

        // ---- O += P @ V ----
#pragma unroll
        for (int ks = 0; ks < 4; ks++) {
            uint32_t a[4];
            ldsm4(a, sP + (qw + lr16)*AROWB + lk8*16 + ks*32);
#pragma unroll
            for (int jp = 0; jp < 4; jp++) {
                uint32_t t[4];
                // trans: rows = keys (ks*16 + sub8 + lane&7), cols = dv (jp*16 + lk8*8)
                ldsm4t(t, sV + (ks*16 + ((lane>>3)&1)*8 + (lane&7))*AROWB
                            + (jp*16 + lk8*8)*2);
                uint32_t b0[2] = {t[0], t[1]};
                uint32_t b1[2] = {t[2], t[3]};
                mma_bf16(o[2*jp],   a, b0);
                mma_bf16(o[2*jp+1], a, b1);
            }
        }
    }

    // ---- normalize + write ----
    const float inv0 = 1.0f / l0, inv1 = 1.0f / l1;
    float* op0 = g_O + ((size_t)b*NQ + q0 + qw + gr)*DM + h*DKH + 2*tc;
    float* op1 = op0 + 8*(size_t)DM;
#pragma unroll
    for (int j = 0; j < 8; j++) {
        *(float2*)(op0 + j*8) = make_float2(o[j][0]*inv0, o[j][1]*inv0);
        *(float2*)(op1 + j*8) = make_float2(o[j][2]*inv1, o[j][3]*inv1);
    }
}

// ============================================================
// LayerNorm: warp per row (512 elems), eps=1e-3
// ============================================================
__global__ void __launch_bounds__(256) ln_kernel(const float* __restrict__ gamma,
                                                 const float* __restrict__ beta,
                                                 float* __restrict__ out)
{
    const int row = blockIdx.x*8 + (threadIdx.x >> 5);
    const int lane = threadIdx.x & 31;
    const float* xr = g_X + (size_t)row*DM;
    float v[16];
    float s = 0.f, s2 = 0.f;
#pragma unroll
    for (int u = 0; u < 4; u++) {
        const float4 t = *(const float4*)(xr + lane*4 + u*128);
        v[4*u+0] = t.x; v[4*u+1] = t.y; v[4*u+2] = t.z; v[4*u+3] = t.w;
        s  += t.x + t.y + t.z + t.w;
        s2 += t.x*t.x + t.y*t.y + t.z*t.z + t.w*t.w;
    }
#pragma unroll
    for (int off = 16; off > 0; off >>= 1) {
        s  += __shfl_xor_sync(0xffffffffu, s,  off);
        s2 += __shfl_xor_sync(0xffffffffu, s2, off);
    }
    const float mu  = s * (1.f/512.f);
    const float var = s2 * (1.f/512.f) - mu*mu;
    const float rs  = rsqrtf(var + 1e-3f);
    float* orow = out + (size_t)row*DM;
#pragma unroll
    for (int u = 0; u < 4; u++) {
        const int d = lane*4 + u*128;
        const float4 g  = *(const float4*)(gamma + d);
        const float4 bt = *(const float4*)(beta + d);
        float4 r;
        r.x = g.x*(v[4*u+0]-mu)*rs + bt.x;
        r.y = g.y*(v[4*u+1]-mu)*rs + bt.y;
        r.z = g.z*(v[4*u+2]-mu)*rs + bt.z;
        r.w = g.w*(v[4*u+3]-mu)*rs + bt.w;
        *(float4*)(orow + d) = r;
    }
}

// ============================================================
extern "C" void kernel_launch(void* const* d_in, const int* in_sizes, int n_in,
                              void* d_out, int out_size)
{
    (void)in_sizes; (void)n_in; (void)out_size;
    const float* queries = (const float*)d_in[0];
    const float* keys    = (const float*)d_in[1];
    const float* values  = (const float*)d_in[2];
    const float* aw      = (const float*)d_in[3];
    const float* bq = (const float*)d_in[5];
    const float* bk = (const float*)d_in[7];
    const float* bv = (const float*)d_in[9];
    const float* bo = (const float*)d_in[11];
    const float* memK = (const float*)d_in[12];
    const float* memV = (const float*)d_in[13];
    const float* gamma = (const float*)d_in[14];
    const float* beta  = (const float*)d_in[15];
    float* out = (float*)d_out;

    cudaFuncSetAttribute(gemm_bf16<0>, cudaFuncAttributeMaxDynamicSharedMemorySize, GEMM_SMEM);
    cudaFuncSetAttribute(gemm_bf16<1>, cudaFuncAttributeMaxDynamicSharedMemorySize, GEMM_SMEM);
    cudaFuncSetAttribute(gemm_bf16<2>, cudaFuncAttributeMaxDynamicSharedMemorySize, GEMM_SMEM);
    cudaFuncSetAttribute(gemm_bf16<3>, cudaFuncAttributeMaxDynamicSharedMemorySize, GEMM_SMEM);

    const dim3 gg(4, 128);
    wt_kernel<<<dim3(16, 16, 4), dim3(32, 8)>>>(
        (const float*)d_in[4], (const float*)d_in[6],
        (const float*)d_in[8], (const float*)d_in[10]);
    memfill_kernel<<<128, 256>>>(memK, memV);
    gemm_bf16<0><<<gg, 256, GEMM_SMEM>>>(queries, 0, bq, nullptr);
    gemm_bf16<1><<<gg, 256, GEMM_SMEM>>>(keys,    1, bk, nullptr);
    gemm_bf16<2><<<gg, 256, GEMM_SMEM>>>(values,  2, bv, nullptr);
    attn_mma_kernel<<<dim3(16, 128), 128>>>(aw);
    gemm_bf16<3><<<gg, 256, GEMM_SMEM>>>(nullptr, 3, bo, queries);
    ln_kernel<<<ROWS/8, 256>>>(gamma, beta, out);
}

// round 7
// speedup vs baseline: 2.0241x; 1.3840x over previous
#include <cuda_runtime.h>
#include <cstdint>
#include <math.h>

// Problem constants
#define NB 16
#define NQ 1024
#define NKK 1024
#define DM 512
#define NH 8
#define DKH 64
#define NM 40
#define NKP 1088          // padded key length: 17 * 64
#define ROWS (NB*NQ)      // 16384

// -------- scratch (static device memory: allowed) --------
__device__ float g_Q[(size_t)NB*NH*NQ*DKH];     // [bh][1024][64] fp32
__device__ float g_K[(size_t)NB*NH*NKP*DKH];    // [bh][1088][64] fp32
__device__ float g_V[(size_t)NB*NH*NKP*DKH];    // [bh][1088][64] fp32
__device__ float g_O[(size_t)ROWS*DM];          // attention out
__device__ float g_X[(size_t)ROWS*DM];          // proj + residual
__device__ float g_Wt[4][(size_t)DM*DM];        // transposed weights [n][k]

// ============================================================
// helpers (base ISA: mma.sync bf16 m16n8k16 + ldmatrix)
// ============================================================
__device__ __forceinline__ uint32_t smem_u32(const void* p) {
    uint32_t a;
    asm("{ .reg .u64 t; cvta.to.shared.u64 t, %1; cvt.u32.u64 %0, t; }"
        : "=r"(a) : "l"(p));
    return a;
}
__device__ __forceinline__ uint32_t pk2(float lo, float hi) {  // {lo,hi} bf16x2
    uint32_t r;
    asm("cvt.rn.bf16x2.f32 %0, %1, %2;" : "=r"(r) : "f"(hi), "f"(lo));
    return r;
}
__device__ __forceinline__ float ex2f(float x) {
    float y;
    asm("ex2.approx.f32 %0, %1;" : "=f"(y) : "f"(x));
    return y;
}
__device__ __forceinline__ void mma_bf16(float* c, const uint32_t* a, const uint32_t* b) {
    asm volatile(
        "mma.sync.aligned.m16n8k16.row.col.f32.bf16.bf16.f32 "
        "{%0,%1,%2,%3}, {%4,%5,%6,%7}, {%8,%9}, {%0,%1,%2,%3};"
        : "+f"(c[0]), "+f"(c[1]), "+f"(c[2]), "+f"(c[3])
        : "r"(a[0]), "r"(a[1]), "r"(a[2]), "r"(a[3]), "r"(b[0]), "r"(b[1]));
}
__device__ __forceinline__ void ldsm4(uint32_t* r, uint32_t addr) {
    asm volatile("ldmatrix.sync.aligned.m8n8.x4.shared.b16 {%0,%1,%2,%3}, [%4];"
                 : "=r"(r[0]), "=r"(r[1]), "=r"(r[2]), "=r"(r[3]) : "r"(addr));
}
__device__ __forceinline__ void ldsm4t(uint32_t* r, uint32_t addr) {
    asm volatile("ldmatrix.sync.aligned.m8n8.x4.trans.shared.b16 {%0,%1,%2,%3}, [%4];"
                 : "=r"(r[0]), "=r"(r[1]), "=r"(r[2]), "=r"(r[3]) : "r"(addr));
}

// ============================================================
// Weight transpose: g_Wt[z][n][k] = W_z[k][n]
// ============================================================
__global__ void wt_kernel(const float* __restrict__ Wq, const float* __restrict__ Wk,
                          const float* __restrict__ Wv, const float* __restrict__ Wo)
{
    __shared__ float t[32][33];
    const int z = blockIdx.z;
    const float* W = (z == 0) ? Wq : (z == 1) ? Wk : (z == 2) ? Wv : Wo;
    const int tx = threadIdx.x, ty = threadIdx.y;
    const int nx = blockIdx.x*32 + tx;
    const int ky = blockIdx.y*32 + ty;
#pragma unroll
    for (int i = 0; i < 32; i += 8)
        t[ty + i][tx] = W[(size_t)(ky + i)*DM + nx];
    __syncthreads();
    const int ok = blockIdx.y*32 + tx;
    const int on = blockIdx.x*32 + ty;
#pragma unroll
    for (int i = 0; i < 32; i += 8)
        g_Wt[z][(size_t)(on + i)*DM + ok] = t[tx][ty + i];
}

// ============================================================
// Memory-slot fill: rows 1024..1087 of g_K/g_V
// ============================================================
__global__ void memfill_kernel(const float* __restrict__ memK,
                               const float* __restrict__ memV)
{
    const int bh = blockIdx.x;
    const int h = bh & 7;
    const float sk = 8.0f;
    const float sv = 6.3245553203367587f;
    for (int idx = threadIdx.x; idx < 64*64; idx += blockDim.x) {
        const int m = idx >> 6;
        const int d = idx & 63;
        float kv = 0.f, vv = 0.f;
        if (m < NM) {
            kv = sk * memK[m*DM + h*DKH + d];
            vv = sv * memV[m*DM + h*DKH + d];
        }
        const size_t o = ((size_t)bh*NKP + 1024 + m)*DKH + d;
        g_K[o] = kv;
        g_V[o] = vv;
    }
}

// ============================================================
// bf16 mma GEMM core (block 128x128, BK=32, 8 warps, dbuf)
// ============================================================
#define GROWB 80                   // bytes per SMEM row (32 bf16 + pad)
#define GBUFB (128*GROWB)          // 10240 B per tile buffer
#define GEMM_SMEM (4*GBUFB)        // A0,A1,B0,B1 = 40960 B

// z: 0=Q 1=K 2=V 3=O-proj(+resid)
template<int FUSED>
__device__ __forceinline__ void gemm_body(const float* __restrict__ Ap,
                                          const float* __restrict__ Wt,
                                          const float* __restrict__ bias,
                                          const float* __restrict__ resid,
                                          int z, char* gsm)
{
    const uint32_t sbase = smem_u32(gsm);
    const int tid = threadIdx.x;
    const int lane = tid & 31, wid = tid >> 5;
    const int wm = (wid & 1) << 6;
    const int wn = (wid >> 1) << 5;
    const int gr = lane >> 2, tc = lane & 3;
    const int m0 = blockIdx.y << 7, n0 = blockIdx.x << 7;

    const int lrow = tid >> 1;
    const int lseg = tid & 1;
    const float* Ag = Ap + (size_t)(m0 + lrow)*DM + lseg*16;
    const float* Bg = Wt + (size_t)(n0 + lrow)*DM + lseg*16;
    const uint32_t a_st = sbase + lrow*GROWB + lseg*32;
    const uint32_t b_st = a_st + 2*GBUFB;

    const int lr16 = lane & 15, lk8 = lane >> 4;
    const uint32_t a_ld = sbase + (wm + lr16)*GROWB + lk8*16;
    const uint32_t b_ld = sbase + 2*GBUFB + (wn + lr16)*GROWB + lk8*16;

    float acc[4][4][4];
#pragma unroll
    for (int i = 0; i < 4; i++)
#pragma unroll
        for (int j = 0; j < 4; j++)
#pragma unroll
            for (int r = 0; r < 4; r++) acc[i][j][r] = 0.f;

    float4 av[4], bv[4];
#pragma unroll
    for (int u = 0; u < 4; u++) {
        av[u] = *(const float4*)(Ag + 4*u);
        bv[u] = *(const float4*)(Bg + 4*u);
    }

    for (int it = 0; it < 16; it++) {
        const uint32_t bufo = (uint32_t)(it & 1)*GBUFB;
        {
            uint32_t p0 = pk2(av[0].x, av[0].y), p1 = pk2(av[0].z, av[0].w);
            uint32_t p2 = pk2(av[1].x, av[1].y), p3 = pk2(av[1].z, av[1].w);
            asm volatile("st.shared.v4.b32 [%0], {%1,%2,%3,%4};"
                         :: "r"(a_st + bufo), "r"(p0), "r"(p1), "r"(p2), "r"(p3));
            p0 = pk2(av[2].x, av[2].y); p1 = pk2(av[2].z, av[2].w);
            p2 = pk2(av[3].x, av[3].y); p3 = pk2(av[3].z, av[3].w);
            asm volatile("st.shared.v4.b32 [%0], {%1,%2,%3,%4};"
                         :: "r"(a_st + bufo + 16), "r"(p0), "r"(p1), "r"(p2), "r"(p3));
            p0 = pk2(bv[0].x, bv[0].y); p1 = pk2(bv[0].z, bv[0].w);
            p2 = pk2(bv[1].x, bv[1].y); p3 = pk2(bv[1].z, bv[1].w);
            asm volatile("st.shared.v4.b32 [%0], {%1,%2,%3,%4};"
                         :: "r"(b_st + bufo), "r"(p0), "r"(p1), "r"(p2), "r"(p3));
            p0 = pk2(bv[2].x, bv[2].y); p1 = pk2(bv[2].z, bv[2].w);
            p2 = pk2(bv[3].x, bv[3].y); p3 = pk2(bv[3].z, bv[3].w);
            asm volatile("st.shared.v4.b32 [%0], {%1,%2,%3,%4};"
                         :: "r"(b_st + bufo + 16), "r"(p0), "r"(p1), "r"(p2), "r"(p3));
        }
        __syncthreads();
        if (it < 15) {
            const int kb = (it + 1)*32;
#pragma unroll
            for (int u = 0; u < 4; u++) {
                av[u] = *(const float4*)(Ag + kb + 4*u);
                bv[u] = *(const float4*)(Bg + kb + 4*u);
            }
        }
#pragma unroll
        for (int ks = 0; ks < 2; ks++) {
            uint32_t a[4][4], b[4][2];
#pragma unroll
            for (int i = 0; i < 4; i++)
                ldsm4(a[i], a_ld + bufo + i*16*GROWB + ks*32);
#pragma unroll
            for (int jp = 0; jp < 2; jp++) {
                uint32_t t[4];
                ldsm4(t, b_ld + bufo + jp*16*GROWB + ks*32);
                b[2*jp][0]   = t[0]; b[2*jp+1][0] = t[1];
                b[2*jp][1]   = t[2]; b[2*jp+1][1] = t[3];
            }
#pragma unroll
            for (int i = 0; i < 4; i++)
#pragma unroll
                for (int j = 0; j < 4; j++)
                    mma_bf16(acc[i][j], a[i], b[j]);
        }
    }

#pragma unroll
    for (int i = 0; i < 4; i++) {
        const int mA = m0 + wm + i*16 + gr;
        const int mB = mA + 8;
#pragma unroll
        for (int j = 0; j < 4; j++) {
            const int n = n0 + wn + j*8 + 2*tc;
            const float b0 = bias[n], b1 = bias[n+1];
            float2 vA = make_float2(acc[i][j][0] + b0, acc[i][j][1] + b1);
            float2 vB = make_float2(acc[i][j][2] + b0, acc[i][j][3] + b1);
            if (!FUSED) {
                const float2 rA = *(const float2*)(resid + (size_t)mA*DM + n);
                const float2 rB = *(const float2*)(resid + (size_t)mB*DM + n);
                vA.x += rA.x; vA.y += rA.y;
                vB.x += rB.x; vB.y += rB.y;
                *(float2*)(&g_X[(size_t)mA*DM + n]) = vA;
                *(float2*)(&g_X[(size_t)mB*DM + n]) = vB;
            } else {
                const int h = n >> 6, d = n & 63;
                const int bbA = mA >> 10, nnA = mA & 1023;
                const int bbB = mB >> 10, nnB = mB & 1023;
                if (z == 0) {
                    *(float2*)(&g_Q[(((size_t)bbA*NH + h)*NQ + nnA)*DKH + d]) = vA;
                    *(float2*)(&g_Q[(((size_t)bbB*NH + h)*NQ + nnB)*DKH + d]) = vB;
                } else if (z == 1) {
                    *(float2*)(&g_K[(((size_t)bbA*NH + h)*NKP + nnA)*DKH + d]) = vA;
                    *(float2*)(&g_K[(((size_t)bbB*NH + h)*NKP + nnB)*DKH + d]) = vB;
                } else {
                    *(float2*)(&g_V[(((size_t)bbA*NH + h)*NKP + nnA)*DKH + d]) = vA;
                    *(float2*)(&g_V[(((size_t)bbB*NH + h)*NKP + nnB)*DKH + d]) = vB;
                }
            }
        }
    }
}

// fused QKV projections: blockIdx.z selects {Q,K,V}
__global__ void __launch_bounds__(256, 2) gemm_qkv(const float* __restrict__ Aq,
                                                   const float* __restrict__ Ak,
                                                   const float* __restrict__ Av,
                                                   const float* __restrict__ bq,
                                                   const float* __restrict__ bk,
                                                   const float* __restrict__ bv)
{
    extern __shared__ char gsm[];
    const int z = blockIdx.z;
    const float* A = (z == 0) ? Aq : (z == 1) ? Ak : Av;
    const float* bias = (z == 0) ? bq : (z == 1) ? bk : bv;
    gemm_body<1>(A, g_Wt[z], bias, nullptr, z, gsm);
}

// output projection + residual
__global__ void __launch_bounds__(256, 2) gemm_out(const float* __restrict__ bias,
                                                   const float* __restrict__ resid)
{
    extern __shared__ char gsm[];
    gemm_body<0>((const float*)g_O, g_Wt[3], bias, resid, 3, gsm);
}

// ============================================================
// bf16 flash attention, block = (b,h) x 128 queries, 8 warps.
// Double-buffered K/V (1 sync/tile). Fixed-reference softmax
// (p = exp2(sc) directly; normalize at the end). P never touches
// SMEM: S C-fragments are repacked into PV A-fragments in regs.
// ============================================================
#define AROWB 144
#define KVBUF (64*AROWB)           // 9216 B (one K or V tile)
#define ABUF  (2*KVBUF)            // 18432 B (K+V buffer pair)

__global__ void __launch_bounds__(256, 2) attn_mma_kernel(const float* __restrict__ AW)
{
    __shared__ char asm_[2*ABUF];  // 36864 B: two (K,V) buffers; Q staged in buf0
    const uint32_t sb = smem_u32(asm_);

    const int tid = threadIdx.x, lane = tid & 31, wid = tid >> 5;
    const int bh = blockIdx.y, b = bh >> 3, h = bh & 7;
    const int q0 = blockIdx.x << 7;            // 128 queries per block
    const int gr = lane >> 2, tc = lane & 3;
    const int qw = wid << 4;                   // 16 q-rows per warp
    const int lr16 = lane & 15, lk8 = lane >> 4;
    const float QSC = 0.125f * 1.4426950408889634f;

    // ---- stage Q (128 rows, scaled into log2 domain) into buf0 ----
    {
        const int r = tid >> 1;                // 0..127
        const int c0 = (tid & 1) << 5;         // 0 or 32
        const float* qp = g_Q + ((size_t)bh*NQ + q0 + r)*DKH + c0;
        const uint32_t qst = sb + r*AROWB + c0*2;
#pragma unroll
        for (int u = 0; u < 2; u++) {
            const float4 t0 = *(const float4*)(qp + 16*u);
            const float4 t1 = *(const float4*)(qp + 16*u + 4);
            const float4 t2 = *(const float4*)(qp + 16*u + 8);
            const float4 t3 = *(const float4*)(qp + 16*u + 12);
            uint32_t p0 = pk2(QSC*t0.x, QSC*t0.y), p1 = pk2(QSC*t0.z, QSC*t0.w);
            uint32_t p2 = pk2(QSC*t1.x, QSC*t1.y), p3 = pk2(QSC*t1.z, QSC*t1.w);
            asm volatile("st.shared.v4.b32 [%0], {%1,%2,%3,%4};"
                         :: "r"(qst + 32*u), "r"(p0), "r"(p1), "r"(p2), "r"(p3));
            p0 = pk2(QSC*t2.x, QSC*t2.y); p1 = pk2(QSC*t2.z, QSC*t2.w);
            p2 = pk2(QSC*t3.x, QSC*t3.y); p3 = pk2(QSC*t3.z, QSC*t3.w);
            asm volatile("st.shared.v4.b32 [%0], {%1,%2,%3,%4};"
                         :: "r"(qst + 32*u + 16), "r"(p0), "r"(p1), "r"(p2), "r"(p3));
        }
    }
    __syncthreads();
    uint32_t qf[4][4];
#pragma unroll
    for (int ks = 0; ks < 4; ks++)
        ldsm4(qf[ks], sb + (qw + lr16)*AROWB + lk8*16 + ks*32);
    __syncthreads();   // all warps done reading Q before buf0 is overwritten

    // ---- K/V staging: 256 threads cover 64 rows x 64 cols ----
    const int rr = tid >> 2;                   // 0..63
    const int cc = (tid & 3) << 4;             // 0,16,32,48
    const float* kgp = g_K + ((size_t)bh*NKP + rr)*DKH + cc;
    const float* vgp = g_V + ((size_t)bh*NKP + rr)*DKH + cc;
    const uint32_t kvo = rr*AROWB + cc*2;

    uint32_t ku[8], vu[8];
#pragma unroll
    for (int u = 0; u < 4; u++) {
        const float4 t = *(const float4*)(kgp + 4*u);
        ku[2*u] = pk2(t.x, t.y); ku[2*u+1] = pk2(t.z, t.w);
        const float4 v = *(const float4*)(vgp + 4*u);
        vu[2*u] = pk2(v.x, v.y); vu[2*u+1] = pk2(v.z, v.w);
    }
    // store tile 0 into buf0
    {
        const uint32_t kst = sb + kvo, vst = sb + KVBUF + kvo;
        asm volatile("st.shared.v4.b32 [%0], {%1,%2,%3,%4};"
                     :: "r"(kst), "r"(ku[0]), "r"(ku[1]), "r"(ku[2]), "r"(ku[3]));
        asm volatile("st.shared.v4.b32 [%0], {%1,%2,%3,%4};"
                     :: "r"(kst + 16), "r"(ku[4]), "r"(ku[5]), "r"(ku[6]), "r"(ku[7]));
        asm volatile("st.shared.v4.b32 [%0], {%1,%2,%3,%4};"
                     :: "r"(vst), "r"(vu[0]), "r"(vu[1]), "r"(vu[2]), "r"(vu[3]));
        asm volatile("st.shared.v4.b32 [%0], {%1,%2,%3,%4};"
                     :: "r"(vst + 16), "r"(vu[4]), "r"(vu[5]), "r"(vu[6]), "r"(vu[7]));
    }
    __syncthreads();

    float o[8][4];
#pragma unroll
    for (int j = 0; j < 8; j++)
#pragma unroll
        for (int r = 0; r < 4; r++) o[j][r] = 0.f;
    float l0 = 0.f, l1 = 0.f;

    for (int kt = 0; kt < 17; kt++) {
        const uint32_t sK = sb + (uint32_t)(kt & 1)*ABUF;
        const uint32_t sV = sK + KVBUF;

        // prefetch next tile into registers (hidden under compute)
        if (kt < 16) {
            const float* kn = kgp + (size_t)(kt+1)*64*DKH;
            const float* vn = vgp + (size_t)(kt+1)*64*DKH;
#pragma unroll
            for (int u = 0; u < 4; u++) {
                const float4 t = *(const float4*)(kn + 4*u);
                ku[2*u] = pk2(t.x, t.y); ku[2*u+1] = pk2(t.z, t.w);
                const float4 v = *(const float4*)(vn + 4*u);
                vu[2*u] = pk2(v.x, v.y); vu[2*u+1] = pk2(v.z, v.w);
            }
        }

        // ---- S = Qs @ K^T (log2 domain) ----
        float sc[8][4];
#pragma unroll
        for (int j = 0; j < 8; j++)
            sc[j][0] = sc[j][1] = sc[j][2] = sc[j][3] = 0.f;
#pragma unroll
        for (int ks = 0; ks < 4; ks++) {
#pragma unroll
            for (int jp = 0; jp < 4; jp++) {
                uint32_t t[4];
                ldsm4(t, sK + (jp*16 + lr16)*AROWB + lk8*16 + ks*32);
                uint32_t b0[2] = {t[0], t[2]};
                uint32_t b1[2] = {t[1], t[3]};
                mma_bf16(sc[2*jp],   qf[ks], b0);
                mma_bf16(sc[2*jp+1], qf[ks], b1);
            }
        }

        // ---- attention_weights / memory mask ----
        if (kt < 16) {
            const float* aw0 = AW + ((size_t)b*NQ + q0 + qw + gr)*NKK + kt*64 + 2*tc;
            const float* aw1 = aw0 + 8*(size_t)NKK;
#pragma unroll
            for (int j = 0; j < 8; j++) {
                const float2 w0 = *(const float2*)(aw0 + j*8);
                const float2 w1 = *(const float2*)(aw1 + j*8);
                sc[j][0] *= w0.x; sc[j][1] *= w0.y;
                sc[j][2] *= w1.x; sc[j][3] *= w1.y;
            }
        } else {
#pragma unroll
            for (int j = 0; j < 8; j++) {
                const int c = j*8 + 2*tc;
                if (c >= NM)     { sc[j][0] = -1e30f; sc[j][2] = -1e30f; }
                if (c + 1 >= NM) { sc[j][1] = -1e30f; sc[j][3] = -1e30f; }
            }
        }

        // ---- fixed-reference softmax: p = exp2(sc); pack PV A-fragments ----
        uint32_t pa[4][4];
        float s0 = 0.f, s1 = 0.f;
#pragma unroll
        for (int t2 = 0; t2 < 4; t2++) {
            const float pA0 = ex2f(sc[2*t2][0]),   pA1 = ex2f(sc[2*t2][1]);
            const float pA2 = ex2f(sc[2*t2][2]),   pA3 = ex2f(sc[2*t2][3]);
            const float pB0 = ex2f(sc[2*t2+1][0]), pB1 = ex2f(sc[2*t2+1][1]);
            const float pB2 = ex2f(sc[2*t2+1][2]), pB3 = ex2f(sc[2*t2+1][3]);
            s0 += (pA0 + pA1) + (pB0 + pB1);
            s1 += (pA2 + pA3) + (pB2 + pB3);
            pa[t2][0] = pk2(pA0, pA1);   // row gr,   k 0..7 of this 16-block
            pa[t2][1] = pk2(pA2, pA3);   // row gr+8, k 0..7
            pa[t2][2] = pk2(pB0, pB1);   // row gr,   k 8..15
            pa[t2][3] = pk2(pB2, pB3);   // row gr+8, k 8..15
        }
        s0 += __shfl_xor_sync(0xffffffffu, s0, 1);
        s0 += __shfl_xor_sync(0xffffffffu, s0, 2);
        s1 += __shfl_xor_sync(0xffffffffu, s1, 1);
        s1 += __shfl_xor_sync(0xffffffffu, s1, 2);
        l0 += s0;
        l1 += s1;

        // ---- O += P @ V (P straight from registers) ----
#pragma unroll
        for (int ks = 0; ks < 4; ks++) {
#pragma unroll
            for (int jp = 0; jp < 4; jp++) {
                uint32_t t[4];
                ldsm4t(t, sV + (ks*16 + ((lane>>3)&1)*8 + (lane&7))*AROWB
                            + (jp*16 + lk8*8)*2);
                uint32_t b0[2] = {t[0], t[1]};
                uint32_t b1[2] = {t[2], t[3]};
                mma_bf16(o[2*jp],   pa[ks], b0);
                mma_bf16(o[2*jp+1], pa[ks], b1);
            }
        }

        // ---- store prefetched tile into the other buffer, then sync ----
        if (kt < 16) {
            const uint32_t kst = sb + (uint32_t)((kt+1) & 1)*ABUF + kvo;
            const uint32_t vst = kst + KVBUF;
            asm volatile("st.shared.v4.b32 [%0], {%1,%2,%3,%4};"
                         :: "r"(kst), "r"(ku[0]), "r"(ku[1]), "r"(ku[2]), "r"(ku[3]));
            asm volatile("st.shared.v4.b32 [%0], {%1,%2,%3,%4};"
                         :: "r"(kst + 16), "r"(ku[4]), "r"(ku[5]), "r"(ku[6]), "r"(ku[7]));
            asm volatile("st.shared.v4.b32 [%0], {%1,%2,%3,%4};"
                         :: "r"(vst), "r"(vu[0]), "r"(vu[1]), "r"(vu[2]), "r"(vu[3]));
            asm volatile("st.shared.v4.b32 [%0], {%1,%2,%3,%4};"
                         :: "r"(vst + 16), "r"(vu[4]), "r"(vu[5]), "r"(vu[6]), "r"(vu[7]));
            __syncthreads();
        }
    }

    // ---- normalize + write ----
    const float inv0 = 1.0f / l0, inv1 = 1.0f / l1;
    float* op0 = g_O + ((size_t)b*NQ + q0 + qw + gr)*DM + h*DKH + 2*tc;
    float* op1 = op0 + 8*(size_t)DM;
#pragma unroll
    for (int j = 0; j < 8; j++) {
        *(float2*)(op0 + j*8) = make_float2(o[j][0]*inv0, o[j][1]*inv0);
        *(float2*)(op1 + j*8) = make_float2(o[j][2]*inv1, o[j][3]*inv1);
    }
}

// ============================================================
// LayerNorm: warp per row (512 elems), eps=1e-3
// ============================================================
__global__ void __launch_bounds__(256) ln_kernel(const float* __restrict__ gamma,
                                                 const float* __restrict__ beta,
                                                 float* __restrict__ out)
{
    const int row = blockIdx.x*8 + (threadIdx.x >> 5);
    const int lane = threadIdx.x & 31;
    const float* xr = g_X + (size_t)row*DM;
    float v[16];
    float s = 0.f, s2 = 0.f;
#pragma unroll
    for (int u = 0; u < 4; u++) {
        const float4 t = *(const float4*)(xr + lane*4 + u*128);
        v[4*u+0] = t.x; v[4*u+1] = t.y; v[4*u+2] = t.z; v[4*u+3] = t.w;
        s  += t.x + t.y + t.z + t.w;
        s2 += t.x*t.x + t.y*t.y + t.z*t.z + t.w*t.w;
    }
#pragma unroll
    for (int off = 16; off > 0; off >>= 1) {
        s  += __shfl_xor_sync(0xffffffffu, s,  off);
        s2 += __shfl_xor_sync(0xffffffffu, s2, off);
    }
    const float mu  = s * (1.f/512.f);
    const float var = s2 * (1.f/512.f) - mu*mu;
    const float rs  = rsqrtf(var + 1e-3f);
    float* orow = out + (size_t)row*DM;
#pragma unroll
    for (int u = 0; u < 4; u++) {
        const int d = lane*4 + u*128;
        const float4 g  = *(const float4*)(gamma + d);
        const float4 bt = *(const float4*)(beta + d);
        float4 r;
        r.x = g.x*(v[4*u+0]-mu)*rs + bt.x;
        r.y = g.y*(v[4*u+1]-mu)*rs + bt.y;
        r.z = g.z*(v[4*u+2]-mu)*rs + bt.z;
        r.w = g.w*(v[4*u+3]-mu)*rs + bt.w;
        *(float4*)(orow + d) = r;
    }
}

// ============================================================
extern "C" void kernel_launch(void* const* d_in, const int* in_sizes, int n_in,
                              void* d_out, int out_size)
{
    (void)in_sizes; (void)n_in; (void)out_size;
    const float* queries = (const float*)d_in[0];
    const float* keys    = (const float*)d_in[1];
    const float* values  = (const float*)d_in[2];
    const float* aw      = (const float*)d_in[3];
    const float* bq = (const float*)d_in[5];
    const float* bk = (const float*)d_in[7];
    const float* bv = (const float*)d_in[9];
    const float* bo = (const float*)d_in[11];
    const float* memK = (const float*)d_in[12];
    const float* memV = (const float*)d_in[13];
    const float* gamma = (const float*)d_in[14];
    const float* beta  = (const float*)d_in[15];
    float* out = (float*)d_out;

    cudaFuncSetAttribute(gemm_qkv, cudaFuncAttributeMaxDynamicSharedMemorySize, GEMM_SMEM);
    cudaFuncSetAttribute(gemm_out, cudaFuncAttributeMaxDynamicSharedMemorySize, GEMM_SMEM);

    wt_kernel<<<dim3(16, 16, 4), dim3(32, 8)>>>(
        (const float*)d_in[4], (const float*)d_in[6],
        (const float*)d_in[8], (const float*)d_in[10]);
    memfill_kernel<<<128, 256>>>(memK, memV);
    gemm_qkv<<<dim3(4, 128, 3), 256, GEMM_SMEM>>>(queries, keys, values, bq, bk, bv);
    attn_mma_kernel<<<dim3(8, 128), 256>>>(aw);
    gemm_out<<<dim3(4, 128), 256, GEMM_SMEM>>>(bo, queries);
    ln_kernel<<<ROWS/8, 256>>>(gamma, beta, out);
}

// round 8
// speedup vs baseline: 2.8896x; 1.4276x over previous
#include <cuda_runtime.h>
#include <cuda_bf16.h>
#include <cstdint>

// Problem constants
#define NB 16
#define NQ 1024
#define NKK 1024
#define DM 512
#define NH 8
#define DKH 64
#define NM 40
#define NKP 1088          // padded key length: 17 * 64
#define ROWS (NB*NQ)      // 16384

// -------- scratch (static device memory: allowed), all 16B-aligned --------
__device__ __align__(256) __nv_bfloat16 g_Ain[3][(size_t)ROWS*DM];    // bf16 inputs
__device__ __align__(256) __nv_bfloat16 g_Qb[(size_t)NB*NH*NQ*DKH];   // pre-scaled bf16
__device__ __align__(256) __nv_bfloat16 g_Kb[(size_t)NB*NH*NKP*DKH];
__device__ __align__(256) __nv_bfloat16 g_Vb[(size_t)NB*NH*NKP*DKH];
__device__ __align__(256) __nv_bfloat16 g_Ob[(size_t)ROWS*DM];
__device__ __align__(256) __nv_bfloat16 g_Wtb[4][(size_t)DM*DM];      // transposed bf16
__device__ __align__(256) float g_X[(size_t)ROWS*DM];

#define QSC (0.125f * 1.4426950408889634f)   // 1/sqrt(dk) * log2(e)

// ============================================================
// helpers
// ============================================================
__device__ __forceinline__ uint32_t smem_u32(const void* p) {
    uint32_t a;
    asm("{ .reg .u64 t; cvta.to.shared.u64 t, %1; cvt.u32.u64 %0, t; }"
        : "=r"(a) : "l"(p));
    return a;
}
__device__ __forceinline__ uint32_t pk2(float lo, float hi) {  // {lo,hi} bf16x2
    uint32_t r;
    asm("cvt.rn.bf16x2.f32 %0, %1, %2;" : "=r"(r) : "f"(hi), "f"(lo));
    return r;
}
__device__ __forceinline__ float ex2f(float x) {
    float y;
    asm("ex2.approx.f32 %0, %1;" : "=f"(y) : "f"(x));
    return y;
}
__device__ __forceinline__ void mma_bf16(float* c, const uint32_t* a, const uint32_t* b) {
    asm volatile(
        "mma.sync.aligned.m16n8k16.row.col.f32.bf16.bf16.f32 "
        "{%0,%1,%2,%3}, {%4,%5,%6,%7}, {%8,%9}, {%0,%1,%2,%3};"
        : "+f"(c[0]), "+f"(c[1]), "+f"(c[2]), "+f"(c[3])
        : "r"(a[0]), "r"(a[1]), "r"(a[2]), "r"(a[3]), "r"(b[0]), "r"(b[1]));
}
__device__ __forceinline__ void ldsm4(uint32_t* r, uint32_t addr) {
    asm volatile("ldmatrix.sync.aligned.m8n8.x4.shared.b16 {%0,%1,%2,%3}, [%4];"
                 : "=r"(r[0]), "=r"(r[1]), "=r"(r[2]), "=r"(r[3]) : "r"(addr));
}
__device__ __forceinline__ void ldsm4t(uint32_t* r, uint32_t addr) {
    asm volatile("ldmatrix.sync.aligned.m8n8.x4.trans.shared.b16 {%0,%1,%2,%3}, [%4];"
                 : "=r"(r[0]), "=r"(r[1]), "=r"(r[2]), "=r"(r[3]) : "r"(addr));
}
__device__ __forceinline__ void cp16(uint32_t dst, const void* src) {
    asm volatile("cp.async.cg.shared.global [%0], [%1], 16;" :: "r"(dst), "l"(src));
}
#define CP_COMMIT() asm volatile("cp.async.commit_group;")
#define CP_WAIT0()  asm volatile("cp.async.wait_group 0;" ::: "memory")
#define CP_WAIT1()  asm volatile("cp.async.wait_group 1;" ::: "memory")
#define CP_WAIT2()  asm volatile("cp.async.wait_group 2;" ::: "memory")

// ============================================================
// Input convert: fp32 -> bf16 (queries/keys/values)
// ============================================================
__global__ void cvt_kernel(const float* __restrict__ q, const float* __restrict__ k,
                           const float* __restrict__ v)
{
    const int z = blockIdx.y;
    const float* src = (z == 0) ? q : (z == 1) ? k : v;
    __nv_bfloat16* dst = g_Ain[z];
    const size_t i = ((size_t)blockIdx.x*blockDim.x + threadIdx.x)*4;
    const float4 t = *(const float4*)(src + i);
    uint2 o;
    o.x = pk2(t.x, t.y);
    o.y = pk2(t.z, t.w);
    *(uint2*)(dst + i) = o;
}

// ============================================================
// Weight transpose + convert: g_Wtb[z][n][k] = bf16(W_z[k][n])
// ============================================================
__global__ void wt_kernel(const float* __restrict__ Wq, const float* __restrict__ Wk,
                          const float* __restrict__ Wv, const float* __restrict__ Wo)
{
    __shared__ float t[32][33];
    const int z = blockIdx.z;
    const float* W = (z == 0) ? Wq : (z == 1) ? Wk : (z == 2) ? Wv : Wo;
    const int tx = threadIdx.x, ty = threadIdx.y;
    const int nx = blockIdx.x*32 + tx;
    const int ky = blockIdx.y*32 + ty;
#pragma unroll
    for (int i = 0; i < 32; i += 8)
        t[ty + i][tx] = W[(size_t)(ky + i)*DM + nx];
    __syncthreads();
    const int ok = blockIdx.y*32 + tx;
    const int on = blockIdx.x*32 + ty;
#pragma unroll
    for (int i = 0; i < 32; i += 8)
        g_Wtb[z][(size_t)(on + i)*DM + ok] = __float2bfloat16(t[tx][ty + i]);
}

// ============================================================
// Memory-slot fill: rows 1024..1087 of g_Kb/g_Vb (bf16)
// ============================================================
__global__ void memfill_kernel(const float* __restrict__ memK,
                               const float* __restrict__ memV)
{
    const int bh = blockIdx.x;
    const int h = bh & 7;
    const float sk = 8.0f;
    const float sv = 6.3245553203367587f;
    for (int idx = threadIdx.x; idx < 64*64; idx += blockDim.x) {
        const int m = idx >> 6;
        const int d = idx & 63;
        float kv = 0.f, vv = 0.f;
        if (m < NM) {
            kv = sk * memK[m*DM + h*DKH + d];
            vv = sv * memV[m*DM + h*DKH + d];
        }
        const size_t o = ((size_t)bh*NKP + 1024 + m)*DKH + d;
        g_Kb[o] = __float2bfloat16(kv);
        g_Vb[o] = __float2bfloat16(vv);
    }
}

// ============================================================
// bf16 mma GEMM (block 128x128, BK=32, 8 warps), cp.async,
// 3-stage ring, one __syncthreads per K-iter.
// ============================================================
#define GROWB 80                   // bytes per SMEM row (32 bf16 + pad)
#define GBUFB (128*GROWB)          // 10240 B per tile stage
#define GEMM_SMEM (6*GBUFB)        // A x3 stages + B x3 stages = 61440 B

// OUTPROJ=0: scatter bf16 to g_Qb/g_Kb/g_Vb (z selects; scale applied)
// OUTPROJ=1: +resid -> g_X fp32
template<int OUTPROJ>
__device__ __forceinline__ void gemm_body(const __nv_bfloat16* __restrict__ Ab,
                                          const __nv_bfloat16* __restrict__ Wb,
                                          const float* __restrict__ bias,
                                          const float* __restrict__ resid,
                                          int z, float scale, char* gsm)
{
    const uint32_t sbase = smem_u32(gsm);
    const int tid = threadIdx.x;
    const int lane = tid & 31, wid = tid >> 5;
    const int wm = (wid & 1) << 6;
    const int wn = (wid >> 1) << 5;
    const int gr = lane >> 2, tc = lane & 3;
    const int m0 = blockIdx.y << 7, n0 = blockIdx.x << 7;

    const int row = tid >> 1, seg = tid & 1;
    const __nv_bfloat16* srcA = Ab + (size_t)(m0 + row)*DM + seg*16;
    const __nv_bfloat16* srcB = Wb + (size_t)(n0 + row)*DM + seg*16;
    const uint32_t dA = sbase + row*GROWB + seg*32;
    const uint32_t dB = dA + 3*GBUFB;

    const int lr16 = lane & 15, lk8 = lane >> 4;

#define G_ISSUE(it, st) do { \
    cp16(dA + (uint32_t)(st)*GBUFB,      srcA + (it)*32); \
    cp16(dA + (uint32_t)(st)*GBUFB + 16, srcA + (it)*32 + 8); \
    cp16(dB + (uint32_t)(st)*GBUFB,      srcB + (it)*32); \
    cp16(dB + (uint32_t)(st)*GBUFB + 16, srcB + (it)*32 + 8); \
    CP_COMMIT(); } while (0)

    float acc[4][4][4];
#pragma unroll
    for (int i = 0; i < 4; i++)
#pragma unroll
        for (int j = 0; j < 4; j++)
#pragma unroll
            for (int r = 0; r < 4; r++) acc[i][j][r] = 0.f;

    G_ISSUE(0, 0);
    G_ISSUE(1, 1);

    for (int it = 0; it < 16; it++) {
        if (it < 15) CP_WAIT1(); else CP_WAIT0();
        __syncthreads();
        if (it + 2 < 16) G_ISSUE(it + 2, (it + 2) % 3);

        const uint32_t so = (uint32_t)(it % 3)*GBUFB;
        const uint32_t a_ld = sbase + so + (wm + lr16)*GROWB + lk8*16;
        const uint32_t b_ld = sbase + 3*GBUFB + so + (wn + lr16)*GROWB + lk8*16;
#pragma unroll
        for (int ks = 0; ks < 2; ks++) {
            uint32_t a[4][4], b[4][2];
#pragma unroll
            for (int i = 0; i < 4; i++)
                ldsm4(a[i], a_ld + i*16*GROWB + ks*32);
#pragma unroll
            for (int jp = 0; jp < 2; jp++) {
                uint32_t t[4];
                ldsm4(t, b_ld + jp*16*GROWB + ks*32);
                b[2*jp][0]   = t[0]; b[2*jp+1][0] = t[1];
                b[2*jp][1]   = t[2]; b[2*jp+1][1] = t[3];
            }
#pragma unroll
            for (int i = 0; i < 4; i++)
#pragma unroll
                for (int j = 0; j < 4; j++)
                    mma_bf16(acc[i][j], a[i], b[j]);
        }
    }
#undef G_ISSUE

#pragma unroll
    for (int i = 0; i < 4; i++) {
        const int mA = m0 + wm + i*16 + gr;
        const int mB = mA + 8;
#pragma unroll
        for (int j = 0; j < 4; j++) {
            const int n = n0 + wn + j*8 + 2*tc;
            const float b0 = bias[n], b1 = bias[n+1];
            if (OUTPROJ) {
                float2 vA = make_float2(acc[i][j][0] + b0, acc[i][j][1] + b1);
                float2 vB = make_float2(acc[i][j][2] + b0, acc[i][j][3] + b1);
                const float2 rA = *(const float2*)(resid + (size_t)mA*DM + n);
                const float2 rB = *(const float2*)(resid + (size_t)mB*DM + n);
                vA.x += rA.x; vA.y += rA.y;
                vB.x += rB.x; vB.y += rB.y;
                *(float2*)(&g_X[(size_t)mA*DM + n]) = vA;
                *(float2*)(&g_X[(size_t)mB*DM + n]) = vB;
            } else {
                const uint32_t pA = pk2((acc[i][j][0] + b0)*scale,
                                        (acc[i][j][1] + b1)*scale);
                const uint32_t pB = pk2((acc[i][j][2] + b0)*scale,
                                        (acc[i][j][3] + b1)*scale);
                const int h = n >> 6, d = n & 63;
                const int bbA = mA >> 10, nnA = mA & 1023;
                const int bbB = mB >> 10, nnB = mB & 1023;
                if (z == 0) {
                    *(uint32_t*)(&g_Qb[(((size_t)bbA*NH + h)*NQ + nnA)*DKH + d]) = pA;
                    *(uint32_t*)(&g_Qb[(((size_t)bbB*NH + h)*NQ + nnB)*DKH + d]) = pB;
                } else if (z == 1) {
                    *(uint32_t*)(&g_Kb[(((size_t)bbA*NH + h)*NKP + nnA)*DKH + d]) = pA;
                    *(uint32_t*)(&g_Kb[(((size_t)bbB*NH + h)*NKP + nnB)*DKH + d]) = pB;
                } else {
                    *(uint32_t*)(&g_Vb[(((size_t)bbA*NH + h)*NKP + nnA)*DKH + d]) = pA;
                    *(uint32_t*)(&g_Vb[(((size_t)bbB*NH + h)*NKP + nnB)*DKH + d]) = pB;
                }
            }
        }
    }
}

__global__ void __launch_bounds__(256, 2) gemm_qkv(const float* __restrict__ bq,
                                                   const float* __restrict__ bk,
                                                   const float* __restrict__ bv)
{
    extern __shared__ char gsm[];
    const int z = blockIdx.z;
    const float* bias = (z == 0) ? bq : (z == 1) ? bk : bv;
    const float scale = (z == 0) ? QSC : 1.0f;
    gemm_body<0>(g_Ain[z], g_Wtb[z], bias, nullptr, z, scale, gsm);
}

__global__ void __launch_bounds__(256, 2) gemm_out(const float* __restrict__ bias,
                                                   const float* __restrict__ resid)
{
    extern __shared__ char gsm[];
    gemm_body<1>(g_Ob, g_Wtb[3], bias, resid, 3, 1.0f, gsm);
}

// ============================================================
// bf16 flash attention: block = (b,h) x 128 queries, 8 warps.
// 3-stage cp.async K/V ring (1 sync/tile). Fixed-reference
// log2-domain softmax; P stays in registers (C-frag -> A-frag).
// ============================================================
#define AROWB 144
#define KVB (64*AROWB)             // 9216 B per K or V tile
#define STGB (2*KVB)               // 18432 B per (K,V) stage
#define ATT_SMEM (3*STGB)          // 55296 B

__global__ void __launch_bounds__(256, 2) attn_mma_kernel(const float* __restrict__ AW)
{
    extern __shared__ char asmm[];
    const uint32_t sb = smem_u32(asmm);

    const int tid = threadIdx.x, lane = tid & 31, wid = tid >> 5;
    const int bh = blockIdx.y, b = bh >> 3, h = bh & 7;
    const int q0 = blockIdx.x << 7;
    const int gr = lane >> 2, tc = lane & 3;
    const int qw = wid << 4;
    const int lr16 = lane & 15, lk8 = lane >> 4;
    const uint32_t sQ = sb + 2*STGB;   // Q staged in stage-2 region

    // ---- issue Q (pre-scaled bf16 in gmem) ----
    {
        const int r = tid >> 1, qs = tid & 1;
        const __nv_bfloat16* src = g_Qb + ((size_t)bh*NQ + q0 + r)*DKH + qs*32;
        const uint32_t dst = sQ + r*AROWB + qs*64;
        cp16(dst, src); cp16(dst + 16, src + 8);
        cp16(dst + 32, src + 16); cp16(dst + 48, src + 24);
        CP_COMMIT();
    }

    // ---- K/V issue config ----
    const int rr = tid >> 2, c4 = tid & 3;
    const __nv_bfloat16* kgp = g_Kb + ((size_t)bh*NKP + rr)*DKH + c4*16;
    const __nv_bfloat16* vgp = g_Vb + ((size_t)bh*NKP + rr)*DKH + c4*16;
    const uint32_t kvdst = rr*AROWB + c4*32;

#define A_ISSUE(kt, st) do { \
    const __nv_bfloat16* ks_ = kgp + (size_t)(kt)*64*DKH; \
    const __nv_bfloat16* vs_ = vgp + (size_t)(kt)*64*DKH; \
    const uint32_t kd = sb + (uint32_t)(st)*STGB + kvdst; \
    cp16(kd, ks_); cp16(kd + 16, ks_ + 8); \
    cp16(kd + KVB, vs_); cp16(kd + KVB + 16, vs_ + 8); \
    CP_COMMIT(); } while (0)

    A_ISSUE(0, 0);
    A_ISSUE(1, 1);
    CP_WAIT2();            // Q arrived
    __syncthreads();

    uint32_t qf[4][4];
#pragma unroll
    for (int ks = 0; ks < 4; ks++)
        ldsm4(qf[ks], sQ + (qw + lr16)*AROWB + lk8*16 + ks*32);
    // stage-2 (Q area) is first overwritten by A_ISSUE(2) at kt=0,
    // which happens after the loop's __syncthreads -> qf reads are safe.

    float o[8][4];
#pragma unroll
    for (int j = 0; j < 8; j++)
#pragma unroll
        for (int r = 0; r < 4; r++) o[j][r] = 0.f;
    float l0 = 0.f, l1 = 0.f;

    for (int kt = 0; kt < 17; kt++) {
        if (kt < 16) CP_WAIT1(); else CP_WAIT0();
        __syncthreads();
        if (kt + 2 <= 16) A_ISSUE(kt + 2, (kt + 2) % 3);

        const uint32_t sK = sb + (uint32_t)(kt % 3)*STGB;
        const uint32_t sV = sK + KVB;

        // ---- S = Qs @ K^T (log2 domain) ----
        float sc[8][4];
#pragma unroll
        for (int j = 0; j < 8; j++)
            sc[j][0] = sc[j][1] = sc[j][2] = sc[j][3] = 0.f;
#pragma unroll
        for (int ks = 0; ks < 4; ks++) {
#pragma unroll
            for (int jp = 0; jp < 4; jp++) {
                uint32_t t[4];
                ldsm4(t, sK + (jp*16 + lr16)*AROWB + lk8*16 + ks*32);
                uint32_t b0[2] = {t[0], t[2]};
                uint32_t b1[2] = {t[1], t[3]};
                mma_bf16(sc[2*jp],   qf[ks], b0);
                mma_bf16(sc[2*jp+1], qf[ks], b1);
            }
        }

        // ---- attention_weights / memory mask ----
        if (kt < 16) {
            const float* aw0 = AW + ((size_t)b*NQ + q0 + qw + gr)*NKK + kt*64 + 2*tc;
            const float* aw1 = aw0 + 8*(size_t)NKK;
#pragma unroll
            for (int j = 0; j < 8; j++) {
                const float2 w0 = *(const float2*)(aw0 + j*8);
                const float2 w1 = *(const float2*)(aw1 + j*8);
                sc[j][0] *= w0.x; sc[j][1] *= w0.y;
                sc[j][2] *= w1.x; sc[j][3] *= w1.y;
            }
        } else {
#pragma unroll
            for (int j = 0; j < 8; j++) {
                const int c = j*8 + 2*tc;
                if (c >= NM)     { sc[j][0] = -1e30f; sc[j][2] = -1e30f; }
                if (c + 1 >= NM) { sc[j][1] = -1e30f; sc[j][3] = -1e30f; }
            }
        }

        // ---- fixed-reference softmax: p = exp2(sc); pack PV A-fragments ----
        uint32_t pa[4][4];
        float s0 = 0.f, s1 = 0.f;
#pragma unroll
        for (int t2 = 0; t2 < 4; t2++) {
            const float pA0 = ex2f(sc[2*t2][0]),   pA1 = ex2f(sc[2*t2][1]);
            const float pA2 = ex2f(sc[2*t2][2]),   pA3 = ex2f(sc[2*t2][3]);
            const float pB0 = ex2f(sc[2*t2+1][0]), pB1 = ex2f(sc[2*t2+1][1]);
            const float pB2 = ex2f(sc[2*t2+1][2]), pB3 = ex2f(sc[2*t2+1][3]);
            s0 += (pA0 + pA1) + (pB0 + pB1);
            s1 += (pA2 + pA3) + (pB2 + pB3);
            pa[t2][0] = pk2(pA0, pA1);
            pa[t2][1] = pk2(pA2, pA3);
            pa[t2][2] = pk2(pB0, pB1);
            pa[t2][3] = pk2(pB2, pB3);
        }
        s0 += __shfl_xor_sync(0xffffffffu, s0, 1);
        s0 += __shfl_xor_sync(0xffffffffu, s0, 2);
        s1 += __shfl_xor_sync(0xffffffffu, s1, 1);
        s1 += __shfl_xor_sync(0xffffffffu, s1, 2);
        l0 += s0;
        l1 += s1;

        // ---- O += P @ V ----
#pragma unroll
        for (int ks = 0; ks < 4; ks++) {
#pragma unroll
            for (int jp = 0; jp < 4; jp++) {
                uint32_t t[4];
                ldsm4t(t, sV + (ks*16 + ((lane>>3)&1)*8 + (lane&7))*AROWB
                            + (jp*16 + lk8*8)*2);
                uint32_t b0[2] = {t[0], t[1]};
                uint32_t b1[2] = {t[2], t[3]};
                mma_bf16(o[2*jp],   pa[ks], b0);
                mma_bf16(o[2*jp+1], pa[ks], b1);
            }
        }
    }
#undef A_ISSUE

    // ---- normalize + write bf16 O ----
    const float inv0 = 1.0f / l0, inv1 = 1.0f / l1;
    __nv_bfloat16* op0 = g_Ob + ((size_t)b*NQ + q0 + qw + gr)*DM + h*DKH + 2*tc;
    __nv_bfloat16* op1 = op0 + 8*(size_t)DM;
#pragma unroll
    for (int j = 0; j < 8; j++) {
        *(uint32_t*)(op0 + j*8) = pk2(o[j][0]*inv0, o[j][1]*inv0);
        *(uint32_t*)(op1 + j*8) = pk2(o[j][2]*inv1, o[j][3]*inv1);
    }
}

// ============================================================
// LayerNorm: warp per row (512 elems), eps=1e-3
// ============================================================
__global__ void __launch_bounds__(256) ln_kernel(const float* __restrict__ gamma,
                                                 const float* __restrict__ beta,
                                                 float* __restrict__ out)
{
    const int row = blockIdx.x*8 + (threadIdx.x >> 5);
    const int lane = threadIdx.x & 31;
    const float* xr = g_X + (size_t)row*DM;
    float v[16];
    float s = 0.f, s2 = 0.f;
#pragma unroll
    for (int u = 0; u < 4; u++) {
        const float4 t = *(const float4*)(xr + lane*4 + u*128);
        v[4*u+0] = t.x; v[4*u+1] = t.y; v[4*u+2] = t.z; v[4*u+3] = t.w;
        s  += t.x + t.y + t.z + t.w;
        s2 += t.x*t.x + t.y*t.y + t.z*t.z + t.w*t.w;
    }
#pragma unroll
    for (int off = 16; off > 0; off >>= 1) {
        s  += __shfl_xor_sync(0xffffffffu, s,  off);
        s2 += __shfl_xor_sync(0xffffffffu, s2, off);
    }
    const float mu  = s * (1.f/512.f);
    const float var = s2 * (1.f/512.f) - mu*mu;
    const float rs  = rsqrtf(var + 1e-3f);
    float* orow = out + (size_t)row*DM;
#pragma unroll
    for (int u = 0; u < 4; u++) {
        const int d = lane*4 + u*128;
        const float4 g  = *(const float4*)(gamma + d);
        const float4 bt = *(const float4*)(beta + d);
        float4 r;
        r.x = g.x*(v[4*u+0]-mu)*rs + bt.x;
        r.y = g.y*(v[4*u+1]-mu)*rs + bt.y;
        r.z = g.z*(v[4*u+2]-mu)*rs + bt.z;
        r.w = g.w*(v[4*u+3]-mu)*rs + bt.w;
        *(float4*)(orow + d) = r;
    }
}

// ============================================================
extern "C" void kernel_launch(void* const* d_in, const int* in_sizes, int n_in,
                              void* d_out, int out_size)
{
    (void)in_sizes; (void)n_in; (void)out_size;
    const float* queries = (const float*)d_in[0];
    const float* keys    = (const float*)d_in[1];
    const float* values  = (const float*)d_in[2];
    const float* aw      = (const float*)d_in[3];
    const float* bq = (const float*)d_in[5];
    const float* bk = (const float*)d_in[7];
    const float* bv = (const float*)d_in[9];
    const float* bo = (const float*)d_in[11];
    const float* memK = (const float*)d_in[12];
    const float* memV = (const float*)d_in[13];
    const float* gamma = (const float*)d_in[14];
    const float* beta  = (const float*)d_in[15];
    float* out = (float*)d_out;

    cudaFuncSetAttribute(gemm_qkv, cudaFuncAttributeMaxDynamicSharedMemorySize, GEMM_SMEM);
    cudaFuncSetAttribute(gemm_out, cudaFuncAttributeMaxDynamicSharedMemorySize, GEMM_SMEM);
    cudaFuncSetAttribute(attn_mma_kernel, cudaFuncAttributeMaxDynamicSharedMemorySize, ATT_SMEM);

    wt_kernel<<<dim3(16, 16, 4), dim3(32, 8)>>>(
        (const float*)d_in[4], (const float*)d_in[6],
        (const float*)d_in[8], (const float*)d_in[10]);
    memfill_kernel<<<128, 256>>>(memK, memV);
    cvt_kernel<<<dim3((ROWS*DM/4)/256, 3), 256>>>(queries, keys, values);
    gemm_qkv<<<dim3(4, 128, 3), 256, GEMM_SMEM>>>(bq, bk, bv);
    attn_mma_kernel<<<dim3(8, 128), 256, ATT_SMEM>>>(aw);
    gemm_out<<<dim3(4, 128), 256, GEMM_SMEM>>>(bo, queries);
    ln_kernel<<<ROWS/8, 256>>>(gamma, beta, out);
}